// round 11
// baseline (speedup 1.0000x reference)
#include <cuda_runtime.h>
#include <math.h>

typedef unsigned long long ull;

// ---------------- problem constants ----------------
#define NIMG   1536            // B*S
#define UNITS  48
#define SENS   1283
#define NB     32
#define NS     48
#define H0 48
#define W0 72

// sc0 half: [icpL=8][row 23][pos 0..35][2ic] ; PSTR=72 floats (288B)
#define PSTR 72
#define PLN  (23*PSTR)          // 1656 floats per plane
#define SC0H (8*PLN)            // 13248 floats
#define W1PSZ (16*9*64*2)       // 18432 floats: [icp16][j9][oc64] ull pairs
#define W1HF  (8*9*64*2)        // 9216 floats (half)
#define W2PSZ (32*9*32*2)       // 18432 floats: [icp32][j9][oc32] ull
#define C1PSZ (11*18*64)        // 12672 floats/img: [y][x(pad18)][ic64]

// ---------------- device scratch ----------------
__device__ float  g_c1h0[(size_t)NIMG * C1PSZ];     // conv1 partial (icpHalf 0)
__device__ float  g_c1h1[(size_t)NIMG * C1PSZ];     // conv1 partial (icpHalf 1)
__device__ float  g_x [(size_t)NIMG * SENS];
__device__ float  g_sn[(size_t)NIMG * UNITS];
__device__ float  g_sd[(size_t)NIMG * UNITS];
__device__ float4 g_sp[SENS * UNITS];
__device__ float4 g_rp[UNITS * UNITS];
__device__ float  g_skn[UNITS], g_skd[UNITS];
__device__ float  g_nc[UNITS], g_dc[UNITS], g_cmt[UNITS];
__device__ float  g_w1p[W1PSZ];
__device__ ull    g_w2p[W2PSZ / 2];

// ---------------- fast math helpers ----------------
__device__ __forceinline__ float rcpf(float x) {
    float y; asm("rcp.approx.f32 %0, %1;" : "=f"(y) : "f"(x)); return y;
}
__device__ __forceinline__ float tanhf_a(float x) {
    float y; asm("tanh.approx.f32 %0, %1;" : "=f"(y) : "f"(x)); return y;
}
__device__ __forceinline__ ull ffma2(ull a, ull b, ull c) {
    ull d; asm("fma.rn.f32x2 %0, %1, %2, %3;" : "=l"(d) : "l"(a), "l"(b), "l"(c));
    return d;
}
__device__ __forceinline__ float2 unpack2(ull v) {
    float2 r; asm("mov.b64 {%0, %1}, %2;" : "=f"(r.x), "=f"(r.y) : "l"(v));
    return r;
}

// ---------------- prep kernels ----------------
__global__ void k_prep_sens(const float* __restrict__ iw, const float* __restrict__ ib,
                            const float* __restrict__ ssig, const float* __restrict__ smu,
                            const float* __restrict__ sw, const float* __restrict__ serev,
                            const int* __restrict__ smask) {
    int idx = blockIdx.x * blockDim.x + threadIdx.x;
    if (idx >= SENS * UNITS) return;
    int k = idx / UNITS;
    float sg = ssig[idx], m = smu[idx];
    float w  = sw[idx] * (float)smask[idx];
    float A = 0.5f * sg * iw[k];
    float C = 0.5f * sg * (ib[k] - m);
    g_sp[idx] = make_float4(A, C, 0.5f * w * serev[idx], 0.5f * w);
}

// rec params + both conv weight repacks in one launch
__global__ void k_prep_recw(const float* __restrict__ sigma, const float* __restrict__ mu,
                            const float* __restrict__ wsyn, const float* __restrict__ erev,
                            const int* __restrict__ mask,
                            const float* __restrict__ w1, const float* __restrict__ w2) {
    int idx = blockIdx.x * blockDim.x + threadIdx.x;
    if (idx < UNITS * UNITS) {
        float sg = sigma[idx], m = mu[idx];
        float w  = wsyn[idx] * (float)mask[idx];
        g_rp[idx] = make_float4(0.5f * sg, -0.5f * sg * m, 0.5f * w * erev[idx], 0.5f * w);
    } else if (idx < 2304 + 16 * 9 * 64) {
        int k = idx - 2304;                       // [icp][j][oc] for conv1
        int icp = k / 576, rem = k % 576, j = rem / 64, oc = rem % 64;
        g_w1p[k * 2 + 0] = w1[(oc * 32 + 2 * icp) * 9 + j];
        g_w1p[k * 2 + 1] = w1[(oc * 32 + 2 * icp + 1) * 9 + j];
    } else if (idx < 2304 + 16 * 9 * 64 + 32 * 9 * 32) {
        int k = idx - 2304 - 16 * 9 * 64;         // [icp][j][oc] for conv2
        int icp = k / 288, rem = k % 288, j = rem / 32, oc = rem % 32;
        float* dst = (float*)g_w2p;
        dst[k * 2 + 0] = w2[(oc * 64 + 2 * icp) * 9 + j];
        dst[k * 2 + 1] = w2[(oc * 64 + 2 * icp + 1) * 9 + j];
    }
}

__global__ void __launch_bounds__(256) k_prep_const(const float* __restrict__ gleak,
                                                    const float* __restrict__ vleak,
                                                    const float* __restrict__ cm) {
    int u = blockIdx.x, tid = threadIdx.x;
    float kn = 0.f, kd = 0.f;
    for (int k = tid; k < SENS; k += 256) {
        float4 p = g_sp[k * UNITS + u];
        kn += p.z; kd += p.w;
    }
    #pragma unroll
    for (int o = 16; o > 0; o >>= 1) {
        kn += __shfl_xor_sync(0xffffffff, kn, o);
        kd += __shfl_xor_sync(0xffffffff, kd, o);
    }
    __shared__ float swn[8], swd[8];
    if ((tid & 31) == 0) { swn[tid >> 5] = kn; swd[tid >> 5] = kd; }
    __syncthreads();
    if (tid == 0) {
        float tn = 0.f, td = 0.f;
        #pragma unroll
        for (int i = 0; i < 8; i++) { tn += swn[i]; td += swd[i]; }
        g_skn[u] = tn; g_skd[u] = td;
        float rn = 0.f, rd = 0.f;
        for (int p = 0; p < UNITS; p++) { float4 q = g_rp[p * UNITS + u]; rn += q.z; rd += q.w; }
        float cmt = cm[u] * 6.f;
        g_cmt[u] = cmt;
        g_nc[u] = gleak[u] * vleak[u] + rn;
        g_dc[u] = cmt + gleak[u] + rd + 1e-8f;
    }
}

// ---------------- k_cnn: conv0 (8 planes) + conv1 partial ----------------
// CTA = (kh, img); 352 threads = 11 oy-warps x 32 lanes; each lane computes
// oc = lane AND oc = lane+32 reusing the same row registers (halves LDS/FLOP).
// 2 CTAs/SM (104.8KB smem). Writes RAW partial sums.
__global__ void __launch_bounds__(352, 2) k_cnn(const float* __restrict__ image,
                                                const float* __restrict__ w0,
                                                const float* __restrict__ b0) {
    extern __shared__ float sm[];
    float* simg = sm;                // 3456
    float* sw0  = sm + 3456;         // 288
    float* sw1  = sm + 3744;         // 9216 (half of w1p: 8 icp x 9 j x 64 oc ull)
    float* sc0  = sm + 12960;        // 13248
    int kh  = blockIdx.x;            // icpHalf
    int img = blockIdx.y;
    int tid = threadIdx.x;

    {   // stage image, conv0 weights, conv1 weight-half (contiguous block)
        const float4* isrc = (const float4*)(image + (size_t)img * (H0 * W0));
        float4* d = (float4*)simg;
        for (int i = tid; i < (H0 * W0) / 4; i += 352) d[i] = isrc[i];
        for (int i = tid; i < 288; i += 352) sw0[i] = w0[i];
        const float4* wsrc = (const float4*)(g_w1p + kh * W1HF);
        float4* dw = (float4*)sw1;
        for (int i = tid; i < W1HF / 4; i += 352) dw[i] = wsrc[i];
    }
    __syncthreads();

    // ---- conv0: 8 planes (global icp = kh*8 + icpL); warp per (icpL, oy), lane = ox ----
    {
        int wid = tid >> 5, lane = tid & 31;
        for (int task = wid; task < 184; task += 11) {
            int icpL = task / 23, oyc = task % 23;
            int icpG = kh * 8 + icpL;
            float we[9], wo[9];
            #pragma unroll
            for (int j = 0; j < 9; j++) {
                we[j] = sw0[(2 * icpG) * 9 + j];
                wo[j] = sw0[(2 * icpG + 1) * 9 + j];
            }
            float be = __ldg(&b0[2 * icpG]), bo = __ldg(&b0[2 * icpG + 1]);
            float2* dst = (float2*)&sc0[icpL * PLN + oyc * PSTR];
            {
                float ae = be, ao = bo;
                #pragma unroll
                for (int ky = 0; ky < 3; ky++) {
                    const float* row = &simg[(2 * oyc + ky) * W0 + 2 * lane];
                    #pragma unroll
                    for (int kx = 0; kx < 3; kx++) {
                        float r = row[kx];
                        ae = fmaf(we[ky * 3 + kx], r, ae);
                        ao = fmaf(wo[ky * 3 + kx], r, ao);
                    }
                }
                dst[lane] = make_float2(fmaxf(ae, 0.f), fmaxf(ao, 0.f));
            }
            if (lane < 3) {
                int ox = 32 + lane;
                float ae = be, ao = bo;
                #pragma unroll
                for (int ky = 0; ky < 3; ky++) {
                    const float* row = &simg[(2 * oyc + ky) * W0 + 2 * ox];
                    #pragma unroll
                    for (int kx = 0; kx < 3; kx++) {
                        float r = row[kx];
                        ae = fmaf(we[ky * 3 + kx], r, ae);
                        ao = fmaf(wo[ky * 3 + kx], r, ao);
                    }
                }
                dst[ox] = make_float2(fmaxf(ae, 0.f), fmaxf(ao, 0.f));
            }
        }
    }
    __syncthreads();

    // ---- conv1 partial: warp = oy, lane -> oc {lane, lane+32}; broadcast rows ----
    int oy = tid >> 5, lane = tid & 31;
    const ull* swq = (const ull*)sw1;
    ull accA[17], accB[17];
    #pragma unroll
    for (int o = 0; o < 17; o++) { accA[o] = 0ull; accB[o] = 0ull; }

    #pragma unroll 1
    for (int icp = 0; icp < 8; icp++) {
        #pragma unroll
        for (int ky = 0; ky < 3; ky++) {
            int r = 2 * oy + ky;
            const ull* rb = (const ull*)&sc0[icp * PLN + r * PSTR];
            ull wa[3], wb[3];
            #pragma unroll
            for (int kx = 0; kx < 3; kx++) {
                int g = (icp * 9 + ky * 3 + kx) * 64;
                wa[kx] = swq[g + lane];
                wb[kx] = swq[g + lane + 32];
            }
            {   // chunk 1: positions 0..12 -> outputs 0..5
                ull t[13];
                const ulonglong2* p2 = (const ulonglong2*)rb;
                #pragma unroll
                for (int j = 0; j < 6; j++) { ulonglong2 v = p2[j]; t[2 * j] = v.x; t[2 * j + 1] = v.y; }
                t[12] = rb[12];
                #pragma unroll
                for (int kx = 0; kx < 3; kx++)
                    #pragma unroll
                    for (int o = 0; o < 6; o++) {
                        accA[o] = ffma2(wa[kx], t[2 * o + kx], accA[o]);
                        accB[o] = ffma2(wb[kx], t[2 * o + kx], accB[o]);
                    }
            }
            {   // chunk 2: positions 12..24 -> outputs 6..11
                ull t[13];
                const ulonglong2* p2 = (const ulonglong2*)(rb + 12);
                #pragma unroll
                for (int j = 0; j < 6; j++) { ulonglong2 v = p2[j]; t[2 * j] = v.x; t[2 * j + 1] = v.y; }
                t[12] = rb[24];
                #pragma unroll
                for (int kx = 0; kx < 3; kx++)
                    #pragma unroll
                    for (int o = 6; o < 12; o++) {
                        accA[o] = ffma2(wa[kx], t[2 * (o - 6) + kx], accA[o]);
                        accB[o] = ffma2(wb[kx], t[2 * (o - 6) + kx], accB[o]);
                    }
            }
            {   // chunk 3: positions 24..34 -> outputs 12..16
                ull t[11];
                const ulonglong2* p2 = (const ulonglong2*)(rb + 24);
                #pragma unroll
                for (int j = 0; j < 5; j++) { ulonglong2 v = p2[j]; t[2 * j] = v.x; t[2 * j + 1] = v.y; }
                t[10] = rb[34];
                #pragma unroll
                for (int kx = 0; kx < 3; kx++)
                    #pragma unroll
                    for (int o = 12; o < 17; o++) {
                        accA[o] = ffma2(wa[kx], t[2 * (o - 12) + kx], accA[o]);
                        accB[o] = ffma2(wb[kx], t[2 * (o - 12) + kx], accB[o]);
                    }
            }
        }
    }

    // epilogue: raw partial sums, layout [y][x18][ic64], coalesced stores
    float* base = (kh ? g_c1h1 : g_c1h0) + (size_t)img * C1PSZ + (oy * 18) * 64;
    #pragma unroll
    for (int o = 0; o < 17; o++) {
        float2 ea = unpack2(accA[o]);
        float2 eb = unpack2(accB[o]);
        base[o * 64 + lane]      = ea.x + ea.y;
        base[o * 64 + lane + 32] = eb.x + eb.y;
    }
    base[17 * 64 + lane] = 0.f;        // pad column
    base[17 * 64 + lane + 32] = 0.f;
}

// ---------------- k_conv2: 2 images/CTA; sum halves + bias/relu -> smem, conv2 -> g_x ----
// 640 threads = 20 warps (10 per image); warp = (oy,p), lane = oc; smem weights.
__global__ void __launch_bounds__(640, 1) k_conv2(const float* __restrict__ b1,
                                                  const float* __restrict__ b2,
                                                  const float* __restrict__ relpos) {
    extern __shared__ float sm2[];
    float* sc1 = sm2;                 // 2 x 12672, layout [y][x18][ic64]
    float* sw2 = sm2 + 2 * C1PSZ;     // 18432
    int img0 = blockIdx.x * 2, tid = threadIdx.x;
    {
        for (int i = tid; i < 2 * (C1PSZ / 4); i += 640) {
            int h = i / (C1PSZ / 4);
            int k = i - h * (C1PSZ / 4);
            const float4* pa = (const float4*)(g_c1h0 + (size_t)(img0 + h) * C1PSZ);
            const float4* pb = (const float4*)(g_c1h1 + (size_t)(img0 + h) * C1PSZ);
            float4 a = pa[k], b = pb[k];
            int oc = (k * 4) & 63;
            float4 v;
            v.x = fmaxf(a.x + b.x + __ldg(&b1[oc + 0]), 0.f);
            v.y = fmaxf(a.y + b.y + __ldg(&b1[oc + 1]), 0.f);
            v.z = fmaxf(a.z + b.z + __ldg(&b1[oc + 2]), 0.f);
            v.w = fmaxf(a.w + b.w + __ldg(&b1[oc + 3]), 0.f);
            ((float4*)sc1)[i] = v;
        }
        const float4* ws = (const float4*)g_w2p;
        float4* dw = (float4*)sw2;
        for (int i = tid; i < W2PSZ / 4; i += 640) dw[i] = ws[i];
    }
    __syncthreads();

    int w    = tid >> 5;          // 0..19
    int h    = w >= 10;           // image select
    int wl   = w - h * 10;        // 0..9
    int oy   = wl >> 1;           // 0..4
    int p    = wl & 1;            // 0..1
    int oc2  = tid & 31;          // 0..31
    int img  = img0 + h;
    const float* in = sc1 + h * C1PSZ;
    const ull* swq = (const ull*)sw2;
    ull acc[4];
    #pragma unroll
    for (int o = 0; o < 4; o++) acc[o] = 0ull;
    #pragma unroll 1
    for (int icq = 0; icq < 16; icq++) {      // 4 input channels per iteration
        #pragma unroll
        for (int ky = 0; ky < 3; ky++) {
            int r = 2 * oy + ky;
            ulonglong2 t[9];
            #pragma unroll
            for (int j = 0; j < 9; j++)
                t[j] = *(const ulonglong2*)&in[(r * 18 + 8 * p + j) * 64 + 4 * icq];
            #pragma unroll
            for (int kx = 0; kx < 3; kx++) {
                ull wk0 = swq[((2 * icq)     * 9 + ky * 3 + kx) * 32 + oc2];
                ull wk1 = swq[((2 * icq + 1) * 9 + ky * 3 + kx) * 32 + oc2];
                #pragma unroll
                for (int o = 0; o < 4; o++) {
                    acc[o] = ffma2(wk0, t[2 * o + kx].x, acc[o]);
                    acc[o] = ffma2(wk1, t[2 * o + kx].y, acc[o]);
                }
            }
        }
    }
    float bb = __ldg(&b2[oc2]);
    float* out = &g_x[(size_t)img * SENS + oc2 * 40 + oy * 8 + 4 * p];
    #pragma unroll
    for (int o = 0; o < 4; o++) {
        float2 e = unpack2(acc[o]);
        out[o] = fmaxf(e.x + e.y + bb, 0.f);
    }
    if (tid < 3)
        g_x[(size_t)img0 * SENS + 1280 + tid] = relpos[(size_t)img0 * 3 + tid];
    if (tid >= 320 && tid < 323)
        g_x[(size_t)(img0 + 1) * SENS + 1280 + (tid - 320)] = relpos[(size_t)(img0 + 1) * 3 + (tid - 320)];
}

// ---------------- sensory synapse precompute: 12 images/block ----------------
#define SCHUNK 96
#define SIMG   12
__global__ void __launch_bounds__(SIMG * UNITS) k_sens() {
    extern __shared__ float sm3[];
    float4* sp = (float4*)sm3;
    float*  xs = sm3 + SCHUNK * UNITS * 4;
    int tid = threadIdx.x;
    int img0 = blockIdx.x * SIMG;
    for (int i = tid; i < SIMG * SENS; i += SIMG * UNITS)
        xs[i] = g_x[(size_t)img0 * SENS + i];
    int u = tid % UNITS, t = tid / UNITS;
    float accn = 0.f, accd = 0.f;
    const float* xrow = &xs[t * SENS];
    for (int k0 = 0; k0 < SENS; k0 += SCHUNK) {
        int C = min(SCHUNK, SENS - k0);
        __syncthreads();
        for (int i = tid; i < C * UNITS; i += SIMG * UNITS) sp[i] = g_sp[k0 * UNITS + i];
        __syncthreads();
        #pragma unroll 4
        for (int kk = 0; kk < C; kk++) {
            float4 p = sp[kk * UNITS + u];
            float xv = xrow[k0 + kk];
            float tt = tanhf_a(fmaf(xv, p.x, p.y));
            accn = fmaf(p.z, tt, accn);
            accd = fmaf(p.w, tt, accd);
        }
    }
    g_sn[(size_t)(img0 + t) * UNITS + u] = g_skn[u] + accn;
    g_sd[(size_t)(img0 + t) * UNITS + u] = g_skd[u] + accd;
}

// ---------------- LTC recurrence + pooling + head ----------------
__global__ void __launch_bounds__(288) k_ltc(const float* __restrict__ wout,
                                             const float* __restrict__ bout,
                                             const float* __restrict__ whead,
                                             const float* __restrict__ bhead,
                                             float* __restrict__ out) {
    extern __shared__ float sm4[];
    float4* rp   = (float4*)sm4;
    float*  sn   = sm4 + 9216;
    float*  sd   = sn + 2304;
    float*  v    = sd + 2304;
    float*  redn = v + 48;
    float*  redd = redn + 288;
    float*  cmt  = redd + 288;
    float*  nc   = cmt + 48;
    float*  dc   = nc + 48;
    float*  outsum = dc + 48;
    int b = blockIdx.x, tid = threadIdx.x;
    for (int i = tid; i < UNITS * UNITS; i += 288) rp[i] = g_rp[i];
    for (int i = tid; i < NS * UNITS; i += 288) {
        sn[i] = g_sn[(size_t)b * NS * UNITS + i];
        sd[i] = g_sd[(size_t)b * NS * UNITS + i];
    }
    if (tid < UNITS) {
        v[tid] = 0.f;
        cmt[tid] = g_cmt[tid];
        nc[tid]  = g_nc[tid];
        dc[tid]  = g_dc[tid];
    }
    if (tid < 4) outsum[tid] = 0.f;
    __syncthreads();
    int u = tid % UNITS, g = tid / UNITS;
    for (int s = 0; s < NS; s++) {
        for (int it = 0; it < 6; it++) {
            float accn = 0.f, accd = 0.f;
            #pragma unroll
            for (int j = 0; j < 8; j++) {
                int p = g * 8 + j;
                float4 q = rp[p * UNITS + u];
                float tt = tanhf_a(fmaf(v[p], q.x, q.y));
                accn = fmaf(q.z, tt, accn);
                accd = fmaf(q.w, tt, accd);
            }
            redn[g * UNITS + u] = accn;
            redd[g * UNITS + u] = accd;
            __syncthreads();
            if (tid < UNITS) {
                float a = 0.f, d = 0.f;
                #pragma unroll
                for (int gg = 0; gg < 6; gg++) { a += redn[gg * UNITS + tid]; d += redd[gg * UNITS + tid]; }
                float vv  = v[tid];
                float num = fmaf(cmt[tid], vv, nc[tid]) + a + sn[s * UNITS + tid];
                float den = dc[tid] + d + sd[s * UNITS + tid];
                v[tid] = num * rcpf(den);
            }
            __syncthreads();
        }
        if (tid < 4) outsum[tid] += v[tid];
    }
    __syncthreads();
    if (tid == 0) {
        float p[4];
        #pragma unroll
        for (int m = 0; m < 4; m++)
            p[m] = outsum[m] * (1.f / 48.f) * wout[m] + bout[m];
        #pragma unroll
        for (int j = 0; j < 2; j++) {
            float h = bhead[j];
            #pragma unroll
            for (int m = 0; m < 4; m++) h = fmaf(p[m], whead[m * 2 + j], h);
            out[b * 2 + j] = tanhf(h);
        }
    }
}

// ---------------- launch ----------------
extern "C" void kernel_launch(void* const* d_in, const int* in_sizes, int n_in,
                              void* d_out, int out_size) {
    const float* image   = (const float*)d_in[0];
    const float* rel_pos = (const float*)d_in[1];
    const float* w0 = (const float*)d_in[2];
    const float* b0 = (const float*)d_in[3];
    const float* w1 = (const float*)d_in[4];
    const float* b1 = (const float*)d_in[5];
    const float* w2 = (const float*)d_in[6];
    const float* b2 = (const float*)d_in[7];
    const float* input_w = (const float*)d_in[8];
    const float* input_b = (const float*)d_in[9];
    const float* gleak = (const float*)d_in[10];
    const float* vleak = (const float*)d_in[11];
    const float* cm    = (const float*)d_in[12];
    const float* sigma = (const float*)d_in[13];
    const float* mu    = (const float*)d_in[14];
    const float* w_syn = (const float*)d_in[15];
    const float* erev  = (const float*)d_in[16];
    const float* s_sigma = (const float*)d_in[17];
    const float* s_mu    = (const float*)d_in[18];
    const float* s_w     = (const float*)d_in[19];
    const float* s_erev  = (const float*)d_in[20];
    const float* w_out = (const float*)d_in[21];
    const float* b_out = (const float*)d_in[22];
    const float* w_head = (const float*)d_in[23];
    const float* b_head = (const float*)d_in[24];
    const int* syn_mask  = (const int*)d_in[25];
    const int* sens_mask = (const int*)d_in[26];
    float* out = (float*)d_out;

    const int SM_CNN  = (3456 + 288 + W1HF + SC0H) * 4;        // 104832
    const int SM_CV2  = (2 * C1PSZ + W2PSZ) * 4;               // 175104
    const int SM_SENS = SCHUNK * UNITS * 16 + SIMG * SENS * 4;
    const int SM_LTC  = (9216 + 2304 + 2304 + 48 + 288 + 288 + 48 + 48 + 48 + 4) * 4;
    cudaFuncSetAttribute(k_cnn,   cudaFuncAttributeMaxDynamicSharedMemorySize, SM_CNN);
    cudaFuncSetAttribute(k_conv2, cudaFuncAttributeMaxDynamicSharedMemorySize, SM_CV2);
    cudaFuncSetAttribute(k_sens,  cudaFuncAttributeMaxDynamicSharedMemorySize, SM_SENS);
    cudaFuncSetAttribute(k_ltc,   cudaFuncAttributeMaxDynamicSharedMemorySize, SM_LTC);

    const int NRW = 2304 + 16 * 9 * 64 + 32 * 9 * 32;
    // k_cnn kept as the 4th launch (the one ncu captures)
    k_prep_sens<<<(SENS * UNITS + 255) / 256, 256>>>(input_w, input_b, s_sigma, s_mu,
                                                     s_w, s_erev, sens_mask);
    k_prep_recw<<<(NRW + 255) / 256, 256>>>(sigma, mu, w_syn, erev, syn_mask, w1, w2);
    k_prep_const<<<UNITS, 256>>>(gleak, vleak, cm);
    k_cnn<<<dim3(2, NIMG), 352, SM_CNN>>>(image, w0, b0);
    k_conv2<<<NIMG / 2, 640, SM_CV2>>>(b1, b2, rel_pos);
    k_sens<<<NIMG / SIMG, SIMG * UNITS, SM_SENS>>>();
    k_ltc<<<NB, 288, SM_LTC>>>(w_out, b_out, w_head, b_head, out);
}

// round 12
// speedup vs baseline: 1.1293x; 1.1293x over previous
#include <cuda_runtime.h>
#include <math.h>

typedef unsigned long long ull;

// ---------------- problem constants ----------------
#define NIMG   1536            // B*S
#define UNITS  48
#define SENS   1283
#define NB     32
#define NS     48
#define H0 48
#define W0 72

// sc0 half: [icpL=8][row 23][pos 0..35][2ic] ; PSTR=72 floats (288B)
#define PSTR 72
#define PLN  (23*PSTR)          // 1656 floats per plane
#define SC0H (8*PLN)            // 13248 floats
#define W1PSZ (16*9*64*2)       // 18432 floats: [icp16][j9][oc64] ull pairs
#define W2PSZ (32*9*32*2)       // 18432 floats: [icp32][j9][oc32] ull
#define C1PSZ (11*18*64)        // 12672 floats/img: [y][x(pad18)][ic64]

// ---------------- device scratch ----------------
__device__ float  g_c1h0[(size_t)NIMG * C1PSZ];     // conv1 partial (icpHalf 0)
__device__ float  g_c1h1[(size_t)NIMG * C1PSZ];     // conv1 partial (icpHalf 1)
__device__ float  g_x [(size_t)NIMG * SENS];
__device__ float  g_sn[(size_t)NIMG * UNITS];
__device__ float  g_sd[(size_t)NIMG * UNITS];
__device__ float4 g_sp[SENS * UNITS];
__device__ float4 g_rp[UNITS * UNITS];
__device__ float  g_skn[UNITS], g_skd[UNITS];
__device__ float  g_nc[UNITS], g_dc[UNITS], g_cmt[UNITS];
__device__ float  g_w1p[W1PSZ];
__device__ ull    g_w2p[W2PSZ / 2];

// ---------------- fast math helpers ----------------
__device__ __forceinline__ float rcpf(float x) {
    float y; asm("rcp.approx.f32 %0, %1;" : "=f"(y) : "f"(x)); return y;
}
__device__ __forceinline__ float tanhf_a(float x) {
    float y; asm("tanh.approx.f32 %0, %1;" : "=f"(y) : "f"(x)); return y;
}
__device__ __forceinline__ ull ffma2(ull a, ull b, ull c) {
    ull d; asm("fma.rn.f32x2 %0, %1, %2, %3;" : "=l"(d) : "l"(a), "l"(b), "l"(c));
    return d;
}
__device__ __forceinline__ float2 unpack2(ull v) {
    float2 r; asm("mov.b64 {%0, %1}, %2;" : "=f"(r.x), "=f"(r.y) : "l"(v));
    return r;
}

// ---------------- prep kernels ----------------
__global__ void k_prep_sens(const float* __restrict__ iw, const float* __restrict__ ib,
                            const float* __restrict__ ssig, const float* __restrict__ smu,
                            const float* __restrict__ sw, const float* __restrict__ serev,
                            const int* __restrict__ smask) {
    int idx = blockIdx.x * blockDim.x + threadIdx.x;
    if (idx >= SENS * UNITS) return;
    int k = idx / UNITS;
    float sg = ssig[idx], m = smu[idx];
    float w  = sw[idx] * (float)smask[idx];
    float A = 0.5f * sg * iw[k];
    float C = 0.5f * sg * (ib[k] - m);
    g_sp[idx] = make_float4(A, C, 0.5f * w * serev[idx], 0.5f * w);
}

// rec params + both conv weight repacks in one launch
__global__ void k_prep_recw(const float* __restrict__ sigma, const float* __restrict__ mu,
                            const float* __restrict__ wsyn, const float* __restrict__ erev,
                            const int* __restrict__ mask,
                            const float* __restrict__ w1, const float* __restrict__ w2) {
    int idx = blockIdx.x * blockDim.x + threadIdx.x;
    if (idx < UNITS * UNITS) {
        float sg = sigma[idx], m = mu[idx];
        float w  = wsyn[idx] * (float)mask[idx];
        g_rp[idx] = make_float4(0.5f * sg, -0.5f * sg * m, 0.5f * w * erev[idx], 0.5f * w);
    } else if (idx < 2304 + 16 * 9 * 64) {
        int k = idx - 2304;                       // [icp][j][oc] for conv1
        int icp = k / 576, rem = k % 576, j = rem / 64, oc = rem % 64;
        g_w1p[k * 2 + 0] = w1[(oc * 32 + 2 * icp) * 9 + j];
        g_w1p[k * 2 + 1] = w1[(oc * 32 + 2 * icp + 1) * 9 + j];
    } else if (idx < 2304 + 16 * 9 * 64 + 32 * 9 * 32) {
        int k = idx - 2304 - 16 * 9 * 64;         // [icp][j][oc] for conv2
        int icp = k / 288, rem = k % 288, j = rem / 32, oc = rem % 32;
        float* dst = (float*)g_w2p;
        dst[k * 2 + 0] = w2[(oc * 64 + 2 * icp) * 9 + j];
        dst[k * 2 + 1] = w2[(oc * 64 + 2 * icp + 1) * 9 + j];
    }
}

__global__ void __launch_bounds__(256) k_prep_const(const float* __restrict__ gleak,
                                                    const float* __restrict__ vleak,
                                                    const float* __restrict__ cm) {
    int u = blockIdx.x, tid = threadIdx.x;
    float kn = 0.f, kd = 0.f;
    for (int k = tid; k < SENS; k += 256) {
        float4 p = g_sp[k * UNITS + u];
        kn += p.z; kd += p.w;
    }
    #pragma unroll
    for (int o = 16; o > 0; o >>= 1) {
        kn += __shfl_xor_sync(0xffffffff, kn, o);
        kd += __shfl_xor_sync(0xffffffff, kd, o);
    }
    __shared__ float swn[8], swd[8];
    if ((tid & 31) == 0) { swn[tid >> 5] = kn; swd[tid >> 5] = kd; }
    __syncthreads();
    if (tid == 0) {
        float tn = 0.f, td = 0.f;
        #pragma unroll
        for (int i = 0; i < 8; i++) { tn += swn[i]; td += swd[i]; }
        g_skn[u] = tn; g_skd[u] = td;
        float rn = 0.f, rd = 0.f;
        for (int p = 0; p < UNITS; p++) { float4 q = g_rp[p * UNITS + u]; rn += q.z; rd += q.w; }
        float cmt = cm[u] * 6.f;
        g_cmt[u] = cmt;
        g_nc[u] = gleak[u] * vleak[u] + rn;
        g_dc[u] = cmt + gleak[u] + rd + 1e-8f;
    }
}

// ---------------- k_cnn: conv0 (8 planes) + conv1 partial, CTA = (img, icpHalf, ocHalf) ----
// 352 threads (11 oy-warps x 32 oc-lanes), 2 CTAs/SM, 80 regs (R10-proven: 416us).
__global__ void __launch_bounds__(352, 2) k_cnn(const float* __restrict__ image,
                                                const float* __restrict__ w0,
                                                const float* __restrict__ b0) {
    extern __shared__ float sm[];
    float* simg = sm;                // 3456
    float* sw0  = sm + 3456;         // 288
    float* sw1  = sm + 3744;         // 4608 (quarter of w1p: 8 icp x 9 j x 32 oc ull)
    float* sc0  = sm + 8352;         // 13248
    int kh  = blockIdx.x & 1;        // icpHalf
    int oh  = blockIdx.x >> 1;       // ocHalf
    int img = blockIdx.y;
    int tid = threadIdx.x;

    {   // stage image, conv0 weights, conv1 weight-quarter
        const float4* isrc = (const float4*)(image + (size_t)img * (H0 * W0));
        float4* d = (float4*)simg;
        for (int i = tid; i < (H0 * W0) / 4; i += 352) d[i] = isrc[i];
        for (int i = tid; i < 288; i += 352) sw0[i] = w0[i];
        const float4* wsrc = (const float4*)g_w1p;
        float4* dw = (float4*)sw1;
        for (int i = tid; i < 1152; i += 352)
            dw[i] = wsrc[(kh * 72 + (i >> 4)) * 32 + oh * 16 + (i & 15)];
    }
    __syncthreads();

    // ---- conv0: 8 planes (global icp = kh*8 + icpL); warp per (icpL, oy), lane = ox ----
    {
        int wid = tid >> 5, lane = tid & 31;
        for (int task = wid; task < 184; task += 11) {
            int icpL = task / 23, oyc = task % 23;
            int icpG = kh * 8 + icpL;
            float we[9], wo[9];
            #pragma unroll
            for (int j = 0; j < 9; j++) {
                we[j] = sw0[(2 * icpG) * 9 + j];
                wo[j] = sw0[(2 * icpG + 1) * 9 + j];
            }
            float be = __ldg(&b0[2 * icpG]), bo = __ldg(&b0[2 * icpG + 1]);
            float2* dst = (float2*)&sc0[icpL * PLN + oyc * PSTR];
            {
                float ae = be, ao = bo;
                #pragma unroll
                for (int ky = 0; ky < 3; ky++) {
                    const float* row = &simg[(2 * oyc + ky) * W0 + 2 * lane];
                    #pragma unroll
                    for (int kx = 0; kx < 3; kx++) {
                        float r = row[kx];
                        ae = fmaf(we[ky * 3 + kx], r, ae);
                        ao = fmaf(wo[ky * 3 + kx], r, ao);
                    }
                }
                dst[lane] = make_float2(fmaxf(ae, 0.f), fmaxf(ao, 0.f));
            }
            if (lane < 3) {
                int ox = 32 + lane;
                float ae = be, ao = bo;
                #pragma unroll
                for (int ky = 0; ky < 3; ky++) {
                    const float* row = &simg[(2 * oyc + ky) * W0 + 2 * ox];
                    #pragma unroll
                    for (int kx = 0; kx < 3; kx++) {
                        float r = row[kx];
                        ae = fmaf(we[ky * 3 + kx], r, ae);
                        ao = fmaf(wo[ky * 3 + kx], r, ao);
                    }
                }
                dst[ox] = make_float2(fmaxf(ae, 0.f), fmaxf(ao, 0.f));
            }
        }
    }
    __syncthreads();

    // ---- conv1 partial: warp = oy, lane = ocL; broadcast rows, coalesced weights ----
    int oy = tid >> 5, lane = tid & 31;
    const ull* swq = (const ull*)sw1;
    ull acc[17];
    #pragma unroll
    for (int o = 0; o < 17; o++) acc[o] = 0ull;

    #pragma unroll 1
    for (int icp = 0; icp < 8; icp++) {
        #pragma unroll
        for (int ky = 0; ky < 3; ky++) {
            int r = 2 * oy + ky;
            const ull* rb = (const ull*)&sc0[icp * PLN + r * PSTR];
            ull wv[3];
            #pragma unroll
            for (int kx = 0; kx < 3; kx++)
                wv[kx] = swq[(icp * 9 + ky * 3 + kx) * 32 + lane];
            {   // chunk 1: positions 0..12 -> outputs 0..5
                ull t[13];
                const ulonglong2* p2 = (const ulonglong2*)rb;
                #pragma unroll
                for (int j = 0; j < 6; j++) { ulonglong2 v = p2[j]; t[2 * j] = v.x; t[2 * j + 1] = v.y; }
                t[12] = rb[12];
                #pragma unroll
                for (int kx = 0; kx < 3; kx++)
                    #pragma unroll
                    for (int o = 0; o < 6; o++)
                        acc[o] = ffma2(wv[kx], t[2 * o + kx], acc[o]);
            }
            {   // chunk 2: positions 12..24 -> outputs 6..11
                ull t[13];
                const ulonglong2* p2 = (const ulonglong2*)(rb + 12);
                #pragma unroll
                for (int j = 0; j < 6; j++) { ulonglong2 v = p2[j]; t[2 * j] = v.x; t[2 * j + 1] = v.y; }
                t[12] = rb[24];
                #pragma unroll
                for (int kx = 0; kx < 3; kx++)
                    #pragma unroll
                    for (int o = 6; o < 12; o++)
                        acc[o] = ffma2(wv[kx], t[2 * (o - 6) + kx], acc[o]);
            }
            {   // chunk 3: positions 24..34 -> outputs 12..16
                ull t[11];
                const ulonglong2* p2 = (const ulonglong2*)(rb + 24);
                #pragma unroll
                for (int j = 0; j < 5; j++) { ulonglong2 v = p2[j]; t[2 * j] = v.x; t[2 * j + 1] = v.y; }
                t[10] = rb[34];
                #pragma unroll
                for (int kx = 0; kx < 3; kx++)
                    #pragma unroll
                    for (int o = 12; o < 17; o++)
                        acc[o] = ffma2(wv[kx], t[2 * (o - 12) + kx], acc[o]);
            }
        }
    }

    // epilogue: raw partial sums, layout [y][x18][ic64], coalesced stores
    int ocG = oh * 32 + lane;
    float* outp = (kh ? g_c1h1 : g_c1h0) + (size_t)img * C1PSZ + (oy * 18) * 64 + ocG;
    #pragma unroll
    for (int o = 0; o < 17; o++) {
        float2 e = unpack2(acc[o]);
        outp[o * 64] = e.x + e.y;
    }
    outp[17 * 64] = 0.f;   // pad column
}

// ---------------- k_conv2: 2 images/CTA; sum halves + bias/relu -> smem, conv2 -> g_x ----
// 640 threads = 20 warps (10 per image); warp = (oy,p), lane = oc; smem weights (no LDG).
__global__ void __launch_bounds__(640, 1) k_conv2(const float* __restrict__ b1,
                                                  const float* __restrict__ b2,
                                                  const float* __restrict__ relpos) {
    extern __shared__ float sm2[];
    float* sc1 = sm2;                 // 2 x 12672, layout [y][x18][ic64]
    float* sw2 = sm2 + 2 * C1PSZ;     // 18432
    int img0 = blockIdx.x * 2, tid = threadIdx.x;
    {
        for (int i = tid; i < 2 * (C1PSZ / 4); i += 640) {
            int h = i / (C1PSZ / 4);
            int k = i - h * (C1PSZ / 4);
            const float4* pa = (const float4*)(g_c1h0 + (size_t)(img0 + h) * C1PSZ);
            const float4* pb = (const float4*)(g_c1h1 + (size_t)(img0 + h) * C1PSZ);
            float4 a = pa[k], b = pb[k];
            int oc = (k * 4) & 63;
            float4 v;
            v.x = fmaxf(a.x + b.x + __ldg(&b1[oc + 0]), 0.f);
            v.y = fmaxf(a.y + b.y + __ldg(&b1[oc + 1]), 0.f);
            v.z = fmaxf(a.z + b.z + __ldg(&b1[oc + 2]), 0.f);
            v.w = fmaxf(a.w + b.w + __ldg(&b1[oc + 3]), 0.f);
            ((float4*)sc1)[i] = v;
        }
        const float4* ws = (const float4*)g_w2p;
        float4* dw = (float4*)sw2;
        for (int i = tid; i < W2PSZ / 4; i += 640) dw[i] = ws[i];
    }
    __syncthreads();

    int w    = tid >> 5;          // 0..19
    int h    = w >= 10;           // image select
    int wl   = w - h * 10;        // 0..9
    int oy   = wl >> 1;           // 0..4
    int p    = wl & 1;            // 0..1
    int oc2  = tid & 31;          // 0..31
    int img  = img0 + h;
    const float* in = sc1 + h * C1PSZ;
    const ull* swq = (const ull*)sw2;
    ull acc[4];
    #pragma unroll
    for (int o = 0; o < 4; o++) acc[o] = 0ull;
    #pragma unroll 1
    for (int icq = 0; icq < 16; icq++) {      // 4 input channels per iteration
        #pragma unroll
        for (int ky = 0; ky < 3; ky++) {
            int r = 2 * oy + ky;
            ulonglong2 t[9];
            #pragma unroll
            for (int j = 0; j < 9; j++)
                t[j] = *(const ulonglong2*)&in[(r * 18 + 8 * p + j) * 64 + 4 * icq];
            #pragma unroll
            for (int kx = 0; kx < 3; kx++) {
                ull wk0 = swq[((2 * icq)     * 9 + ky * 3 + kx) * 32 + oc2];
                ull wk1 = swq[((2 * icq + 1) * 9 + ky * 3 + kx) * 32 + oc2];
                #pragma unroll
                for (int o = 0; o < 4; o++) {
                    acc[o] = ffma2(wk0, t[2 * o + kx].x, acc[o]);
                    acc[o] = ffma2(wk1, t[2 * o + kx].y, acc[o]);
                }
            }
        }
    }
    float bb = __ldg(&b2[oc2]);
    float* out = &g_x[(size_t)img * SENS + oc2 * 40 + oy * 8 + 4 * p];
    #pragma unroll
    for (int o = 0; o < 4; o++) {
        float2 e = unpack2(acc[o]);
        out[o] = fmaxf(e.x + e.y + bb, 0.f);
    }
    if (tid < 3)
        g_x[(size_t)img0 * SENS + 1280 + tid] = relpos[(size_t)img0 * 3 + tid];
    if (tid >= 320 && tid < 323)
        g_x[(size_t)(img0 + 1) * SENS + 1280 + (tid - 320)] = relpos[(size_t)(img0 + 1) * 3 + (tid - 320)];
}

// ---------------- sensory synapse precompute: 12 images/block ----------------
#define SCHUNK 96
#define SIMG   12
__global__ void __launch_bounds__(SIMG * UNITS) k_sens() {
    extern __shared__ float sm3[];
    float4* sp = (float4*)sm3;
    float*  xs = sm3 + SCHUNK * UNITS * 4;
    int tid = threadIdx.x;
    int img0 = blockIdx.x * SIMG;
    for (int i = tid; i < SIMG * SENS; i += SIMG * UNITS)
        xs[i] = g_x[(size_t)img0 * SENS + i];
    int u = tid % UNITS, t = tid / UNITS;
    float accn = 0.f, accd = 0.f;
    const float* xrow = &xs[t * SENS];
    for (int k0 = 0; k0 < SENS; k0 += SCHUNK) {
        int C = min(SCHUNK, SENS - k0);
        __syncthreads();
        for (int i = tid; i < C * UNITS; i += SIMG * UNITS) sp[i] = g_sp[k0 * UNITS + i];
        __syncthreads();
        #pragma unroll 4
        for (int kk = 0; kk < C; kk++) {
            float4 p = sp[kk * UNITS + u];
            float xv = xrow[k0 + kk];
            float tt = tanhf_a(fmaf(xv, p.x, p.y));
            accn = fmaf(p.z, tt, accn);
            accd = fmaf(p.w, tt, accd);
        }
    }
    g_sn[(size_t)(img0 + t) * UNITS + u] = g_skn[u] + accn;
    g_sd[(size_t)(img0 + t) * UNITS + u] = g_skd[u] + accd;
}

// ---------------- LTC recurrence + pooling + head ----------------
__global__ void __launch_bounds__(288) k_ltc(const float* __restrict__ wout,
                                             const float* __restrict__ bout,
                                             const float* __restrict__ whead,
                                             const float* __restrict__ bhead,
                                             float* __restrict__ out) {
    extern __shared__ float sm4[];
    float4* rp   = (float4*)sm4;
    float*  sn   = sm4 + 9216;
    float*  sd   = sn + 2304;
    float*  v    = sd + 2304;
    float*  redn = v + 48;
    float*  redd = redn + 288;
    float*  cmt  = redd + 288;
    float*  nc   = cmt + 48;
    float*  dc   = nc + 48;
    float*  outsum = dc + 48;
    int b = blockIdx.x, tid = threadIdx.x;
    for (int i = tid; i < UNITS * UNITS; i += 288) rp[i] = g_rp[i];
    for (int i = tid; i < NS * UNITS; i += 288) {
        sn[i] = g_sn[(size_t)b * NS * UNITS + i];
        sd[i] = g_sd[(size_t)b * NS * UNITS + i];
    }
    if (tid < UNITS) {
        v[tid] = 0.f;
        cmt[tid] = g_cmt[tid];
        nc[tid]  = g_nc[tid];
        dc[tid]  = g_dc[tid];
    }
    if (tid < 4) outsum[tid] = 0.f;
    __syncthreads();
    int u = tid % UNITS, g = tid / UNITS;
    for (int s = 0; s < NS; s++) {
        for (int it = 0; it < 6; it++) {
            float accn = 0.f, accd = 0.f;
            #pragma unroll
            for (int j = 0; j < 8; j++) {
                int p = g * 8 + j;
                float4 q = rp[p * UNITS + u];
                float tt = tanhf_a(fmaf(v[p], q.x, q.y));
                accn = fmaf(q.z, tt, accn);
                accd = fmaf(q.w, tt, accd);
            }
            redn[g * UNITS + u] = accn;
            redd[g * UNITS + u] = accd;
            __syncthreads();
            if (tid < UNITS) {
                float a = 0.f, d = 0.f;
                #pragma unroll
                for (int gg = 0; gg < 6; gg++) { a += redn[gg * UNITS + tid]; d += redd[gg * UNITS + tid]; }
                float vv  = v[tid];
                float num = fmaf(cmt[tid], vv, nc[tid]) + a + sn[s * UNITS + tid];
                float den = dc[tid] + d + sd[s * UNITS + tid];
                v[tid] = num * rcpf(den);
            }
            __syncthreads();
        }
        if (tid < 4) outsum[tid] += v[tid];
    }
    __syncthreads();
    if (tid == 0) {
        float p[4];
        #pragma unroll
        for (int m = 0; m < 4; m++)
            p[m] = outsum[m] * (1.f / 48.f) * wout[m] + bout[m];
        #pragma unroll
        for (int j = 0; j < 2; j++) {
            float h = bhead[j];
            #pragma unroll
            for (int m = 0; m < 4; m++) h = fmaf(p[m], whead[m * 2 + j], h);
            out[b * 2 + j] = tanhf(h);
        }
    }
}

// ---------------- launch ----------------
extern "C" void kernel_launch(void* const* d_in, const int* in_sizes, int n_in,
                              void* d_out, int out_size) {
    const float* image   = (const float*)d_in[0];
    const float* rel_pos = (const float*)d_in[1];
    const float* w0 = (const float*)d_in[2];
    const float* b0 = (const float*)d_in[3];
    const float* w1 = (const float*)d_in[4];
    const float* b1 = (const float*)d_in[5];
    const float* w2 = (const float*)d_in[6];
    const float* b2 = (const float*)d_in[7];
    const float* input_w = (const float*)d_in[8];
    const float* input_b = (const float*)d_in[9];
    const float* gleak = (const float*)d_in[10];
    const float* vleak = (const float*)d_in[11];
    const float* cm    = (const float*)d_in[12];
    const float* sigma = (const float*)d_in[13];
    const float* mu    = (const float*)d_in[14];
    const float* w_syn = (const float*)d_in[15];
    const float* erev  = (const float*)d_in[16];
    const float* s_sigma = (const float*)d_in[17];
    const float* s_mu    = (const float*)d_in[18];
    const float* s_w     = (const float*)d_in[19];
    const float* s_erev  = (const float*)d_in[20];
    const float* w_out = (const float*)d_in[21];
    const float* b_out = (const float*)d_in[22];
    const float* w_head = (const float*)d_in[23];
    const float* b_head = (const float*)d_in[24];
    const int* syn_mask  = (const int*)d_in[25];
    const int* sens_mask = (const int*)d_in[26];
    float* out = (float*)d_out;

    const int SM_CNN  = (3456 + 288 + 4608 + SC0H) * 4;        // 86400
    const int SM_CV2  = (2 * C1PSZ + W2PSZ) * 4;               // 175104
    const int SM_SENS = SCHUNK * UNITS * 16 + SIMG * SENS * 4;
    const int SM_LTC  = (9216 + 2304 + 2304 + 48 + 288 + 288 + 48 + 48 + 48 + 4) * 4;
    cudaFuncSetAttribute(k_cnn,   cudaFuncAttributeMaxDynamicSharedMemorySize, SM_CNN);
    cudaFuncSetAttribute(k_conv2, cudaFuncAttributeMaxDynamicSharedMemorySize, SM_CV2);
    cudaFuncSetAttribute(k_sens,  cudaFuncAttributeMaxDynamicSharedMemorySize, SM_SENS);
    cudaFuncSetAttribute(k_ltc,   cudaFuncAttributeMaxDynamicSharedMemorySize, SM_LTC);

    const int NRW = 2304 + 16 * 9 * 64 + 32 * 9 * 32;
    // k_cnn kept as the 4th launch (the one ncu captures)
    k_prep_sens<<<(SENS * UNITS + 255) / 256, 256>>>(input_w, input_b, s_sigma, s_mu,
                                                     s_w, s_erev, sens_mask);
    k_prep_recw<<<(NRW + 255) / 256, 256>>>(sigma, mu, w_syn, erev, syn_mask, w1, w2);
    k_prep_const<<<UNITS, 256>>>(gleak, vleak, cm);
    k_cnn<<<dim3(4, NIMG), 352, SM_CNN>>>(image, w0, b0);
    k_conv2<<<NIMG / 2, 640, SM_CV2>>>(b1, b2, rel_pos);
    k_sens<<<NIMG / SIMG, SIMG * UNITS, SM_SENS>>>();
    k_ltc<<<NB, 288, SM_LTC>>>(w_out, b_out, w_head, b_head, out);
}

// round 14
// speedup vs baseline: 1.1702x; 1.0362x over previous
#include <cuda_runtime.h>
#include <math.h>

typedef unsigned long long ull;

// ---------------- problem constants ----------------
#define NIMG   1536            // B*S
#define UNITS  48
#define SENS   1283
#define NB     32
#define NS     48
#define H0 48
#define W0 72

// sc0 half: [icpL=8][row 23][pos 0..35][2ic] ; PSTR=72 floats (288B)
#define PSTR 72
#define PLN  (23*PSTR)          // 1656 floats per plane
#define SC0H (8*PLN)            // 13248 floats
#define W1PSZ (16*9*64*2)       // 18432 floats: [icp16][j9][oc64] ull pairs
#define W2PSZ (32*9*32*2)       // 18432 floats: [icp32][j9][oc32] ull
#define C1PSZ (11*17*64)        // 11968 floats/img: [y][x17][ic64] (no pad)

// ---------------- device scratch ----------------
__device__ float  g_c1h0[(size_t)NIMG * C1PSZ];     // conv1 partial (icpHalf 0)
__device__ float  g_c1h1[(size_t)NIMG * C1PSZ];     // conv1 partial (icpHalf 1)
__device__ int    g_cnt [NIMG];                     // per-image arrival counter
__device__ float  g_x [(size_t)NIMG * SENS];
__device__ float  g_sn[(size_t)NIMG * UNITS];
__device__ float  g_sd[(size_t)NIMG * UNITS];
__device__ float4 g_sp[SENS * UNITS];
__device__ float4 g_rp[UNITS * UNITS];
__device__ float  g_skn[UNITS], g_skd[UNITS];
__device__ float  g_nc[UNITS], g_dc[UNITS], g_cmt[UNITS];
__device__ float  g_w1p[W1PSZ];
__device__ ull    g_w2p[W2PSZ / 2];

// ---------------- fast math helpers ----------------
__device__ __forceinline__ float rcpf(float x) {
    float y; asm("rcp.approx.f32 %0, %1;" : "=f"(y) : "f"(x)); return y;
}
__device__ __forceinline__ float tanhf_a(float x) {
    float y; asm("tanh.approx.f32 %0, %1;" : "=f"(y) : "f"(x)); return y;
}
__device__ __forceinline__ ull ffma2(ull a, ull b, ull c) {
    ull d; asm("fma.rn.f32x2 %0, %1, %2, %3;" : "=l"(d) : "l"(a), "l"(b), "l"(c));
    return d;
}
__device__ __forceinline__ float2 unpack2(ull v) {
    float2 r; asm("mov.b64 {%0, %1}, %2;" : "=f"(r.x), "=f"(r.y) : "l"(v));
    return r;
}
__device__ __forceinline__ float4 ldcg4(const float4* p) {
    float4 v;
    asm volatile("ld.global.cg.v4.f32 {%0,%1,%2,%3}, [%4];"
                 : "=f"(v.x), "=f"(v.y), "=f"(v.z), "=f"(v.w) : "l"(p));
    return v;
}

// ---------------- prep kernels ----------------
__global__ void k_prep_sens(const float* __restrict__ iw, const float* __restrict__ ib,
                            const float* __restrict__ ssig, const float* __restrict__ smu,
                            const float* __restrict__ sw, const float* __restrict__ serev,
                            const int* __restrict__ smask) {
    int idx = blockIdx.x * blockDim.x + threadIdx.x;
    if (idx >= SENS * UNITS) return;
    if (idx < NIMG) g_cnt[idx] = 0;          // reset arrival counters every launch
    int k = idx / UNITS;
    float sg = ssig[idx], m = smu[idx];
    float w  = sw[idx] * (float)smask[idx];
    float A = 0.5f * sg * iw[k];
    float C = 0.5f * sg * (ib[k] - m);
    g_sp[idx] = make_float4(A, C, 0.5f * w * serev[idx], 0.5f * w);
}

// rec params + both conv weight repacks in one launch
__global__ void k_prep_recw(const float* __restrict__ sigma, const float* __restrict__ mu,
                            const float* __restrict__ wsyn, const float* __restrict__ erev,
                            const int* __restrict__ mask,
                            const float* __restrict__ w1, const float* __restrict__ w2) {
    int idx = blockIdx.x * blockDim.x + threadIdx.x;
    if (idx < UNITS * UNITS) {
        float sg = sigma[idx], m = mu[idx];
        float w  = wsyn[idx] * (float)mask[idx];
        g_rp[idx] = make_float4(0.5f * sg, -0.5f * sg * m, 0.5f * w * erev[idx], 0.5f * w);
    } else if (idx < 2304 + 16 * 9 * 64) {
        int k = idx - 2304;                       // [icp][j][oc] for conv1
        int icp = k / 576, rem = k % 576, j = rem / 64, oc = rem % 64;
        g_w1p[k * 2 + 0] = w1[(oc * 32 + 2 * icp) * 9 + j];
        g_w1p[k * 2 + 1] = w1[(oc * 32 + 2 * icp + 1) * 9 + j];
    } else if (idx < 2304 + 16 * 9 * 64 + 32 * 9 * 32) {
        int k = idx - 2304 - 16 * 9 * 64;         // [icp][j][oc] for conv2
        int icp = k / 288, rem = k % 288, j = rem / 32, oc = rem % 32;
        float* dst = (float*)g_w2p;
        dst[k * 2 + 0] = w2[(oc * 64 + 2 * icp) * 9 + j];
        dst[k * 2 + 1] = w2[(oc * 64 + 2 * icp + 1) * 9 + j];
    }
}

__global__ void __launch_bounds__(256) k_prep_const(const float* __restrict__ gleak,
                                                    const float* __restrict__ vleak,
                                                    const float* __restrict__ cm) {
    int u = blockIdx.x, tid = threadIdx.x;
    float kn = 0.f, kd = 0.f;
    for (int k = tid; k < SENS; k += 256) {
        float4 p = g_sp[k * UNITS + u];
        kn += p.z; kd += p.w;
    }
    #pragma unroll
    for (int o = 16; o > 0; o >>= 1) {
        kn += __shfl_xor_sync(0xffffffff, kn, o);
        kd += __shfl_xor_sync(0xffffffff, kd, o);
    }
    __shared__ float swn[8], swd[8];
    if ((tid & 31) == 0) { swn[tid >> 5] = kn; swd[tid >> 5] = kd; }
    __syncthreads();
    if (tid == 0) {
        float tn = 0.f, td = 0.f;
        #pragma unroll
        for (int i = 0; i < 8; i++) { tn += swn[i]; td += swd[i]; }
        g_skn[u] = tn; g_skd[u] = td;
        float rn = 0.f, rd = 0.f;
        for (int p = 0; p < UNITS; p++) { float4 q = g_rp[p * UNITS + u]; rn += q.z; rd += q.w; }
        float cmt = cm[u] * 6.f;
        g_cmt[u] = cmt;
        g_nc[u] = gleak[u] * vleak[u] + rn;
        g_dc[u] = cmt + gleak[u] + rd + 1e-8f;
    }
}

// ---------------- k_cnn: conv0 + conv1 partial + (last CTA) conv2 ----------------
// CTA = (img, icpHalf, ocHalf); 352 threads, 2 CTAs/SM. Last-arriving CTA per image
// sums the 4 partials (L2-hot) and runs conv2 in-place.
__global__ void __launch_bounds__(352, 2) k_cnn(const float* __restrict__ image,
                                                const float* __restrict__ w0,
                                                const float* __restrict__ b0,
                                                const float* __restrict__ b1,
                                                const float* __restrict__ b2,
                                                const float* __restrict__ relpos) {
    extern __shared__ float sm[];
    float* simg = sm;                // 3456
    float* sw0  = sm + 3456;         // 288
    float* sw1  = sm + 3744;         // 4608 (quarter of w1p)
    float* sc0  = sm + 8352;         // 13248   (total 21600 floats)
    __shared__ int s_last;
    int kh  = blockIdx.x & 1;        // icpHalf
    int oh  = blockIdx.x >> 1;       // ocHalf
    int img = blockIdx.y;
    int tid = threadIdx.x;

    {   // stage image, conv0 weights, conv1 weight-quarter
        const float4* isrc = (const float4*)(image + (size_t)img * (H0 * W0));
        float4* d = (float4*)simg;
        for (int i = tid; i < (H0 * W0) / 4; i += 352) d[i] = isrc[i];
        for (int i = tid; i < 288; i += 352) sw0[i] = w0[i];
        const float4* wsrc = (const float4*)g_w1p;
        float4* dw = (float4*)sw1;
        for (int i = tid; i < 1152; i += 352)
            dw[i] = wsrc[(kh * 72 + (i >> 4)) * 32 + oh * 16 + (i & 15)];
    }
    __syncthreads();

    // ---- conv0: 8 planes (global icp = kh*8 + icpL); warp per (icpL, oy), lane = ox ----
    {
        int wid = tid >> 5, lane = tid & 31;
        for (int task = wid; task < 184; task += 11) {
            int icpL = task / 23, oyc = task % 23;
            int icpG = kh * 8 + icpL;
            float we[9], wo[9];
            #pragma unroll
            for (int j = 0; j < 9; j++) {
                we[j] = sw0[(2 * icpG) * 9 + j];
                wo[j] = sw0[(2 * icpG + 1) * 9 + j];
            }
            float be = __ldg(&b0[2 * icpG]), bo = __ldg(&b0[2 * icpG + 1]);
            float2* dst = (float2*)&sc0[icpL * PLN + oyc * PSTR];
            {
                float ae = be, ao = bo;
                #pragma unroll
                for (int ky = 0; ky < 3; ky++) {
                    const float* row = &simg[(2 * oyc + ky) * W0 + 2 * lane];
                    #pragma unroll
                    for (int kx = 0; kx < 3; kx++) {
                        float r = row[kx];
                        ae = fmaf(we[ky * 3 + kx], r, ae);
                        ao = fmaf(wo[ky * 3 + kx], r, ao);
                    }
                }
                dst[lane] = make_float2(fmaxf(ae, 0.f), fmaxf(ao, 0.f));
            }
            if (lane < 3) {
                int ox = 32 + lane;
                float ae = be, ao = bo;
                #pragma unroll
                for (int ky = 0; ky < 3; ky++) {
                    const float* row = &simg[(2 * oyc + ky) * W0 + 2 * ox];
                    #pragma unroll
                    for (int kx = 0; kx < 3; kx++) {
                        float r = row[kx];
                        ae = fmaf(we[ky * 3 + kx], r, ae);
                        ao = fmaf(wo[ky * 3 + kx], r, ao);
                    }
                }
                dst[ox] = make_float2(fmaxf(ae, 0.f), fmaxf(ao, 0.f));
            }
        }
    }
    __syncthreads();

    // ---- conv1 partial: warp = oy, lane = ocL; broadcast rows, coalesced weights ----
    int oy = tid >> 5, lane = tid & 31;
    {
        const ull* swq = (const ull*)sw1;
        ull acc[17];
        #pragma unroll
        for (int o = 0; o < 17; o++) acc[o] = 0ull;

        #pragma unroll 1
        for (int icp = 0; icp < 8; icp++) {
            #pragma unroll
            for (int ky = 0; ky < 3; ky++) {
                int r = 2 * oy + ky;
                const ull* rb = (const ull*)&sc0[icp * PLN + r * PSTR];
                ull wv[3];
                #pragma unroll
                for (int kx = 0; kx < 3; kx++)
                    wv[kx] = swq[(icp * 9 + ky * 3 + kx) * 32 + lane];
                {   // chunk 1: positions 0..12 -> outputs 0..5
                    ull t[13];
                    const ulonglong2* p2 = (const ulonglong2*)rb;
                    #pragma unroll
                    for (int j = 0; j < 6; j++) { ulonglong2 v = p2[j]; t[2 * j] = v.x; t[2 * j + 1] = v.y; }
                    t[12] = rb[12];
                    #pragma unroll
                    for (int kx = 0; kx < 3; kx++)
                        #pragma unroll
                        for (int o = 0; o < 6; o++)
                            acc[o] = ffma2(wv[kx], t[2 * o + kx], acc[o]);
                }
                {   // chunk 2: positions 12..24 -> outputs 6..11
                    ull t[13];
                    const ulonglong2* p2 = (const ulonglong2*)(rb + 12);
                    #pragma unroll
                    for (int j = 0; j < 6; j++) { ulonglong2 v = p2[j]; t[2 * j] = v.x; t[2 * j + 1] = v.y; }
                    t[12] = rb[24];
                    #pragma unroll
                    for (int kx = 0; kx < 3; kx++)
                        #pragma unroll
                        for (int o = 6; o < 12; o++)
                            acc[o] = ffma2(wv[kx], t[2 * (o - 6) + kx], acc[o]);
                }
                {   // chunk 3: positions 24..34 -> outputs 12..16
                    ull t[11];
                    const ulonglong2* p2 = (const ulonglong2*)(rb + 24);
                    #pragma unroll
                    for (int j = 0; j < 5; j++) { ulonglong2 v = p2[j]; t[2 * j] = v.x; t[2 * j + 1] = v.y; }
                    t[10] = rb[34];
                    #pragma unroll
                    for (int kx = 0; kx < 3; kx++)
                        #pragma unroll
                        for (int o = 12; o < 17; o++)
                            acc[o] = ffma2(wv[kx], t[2 * (o - 12) + kx], acc[o]);
                }
            }
        }

        // epilogue: raw partial sums, layout [y][x17][ic64], coalesced stores
        int ocG = oh * 32 + lane;
        float* outp = (kh ? g_c1h1 : g_c1h0) + (size_t)img * C1PSZ + (oy * 17) * 64 + ocG;
        #pragma unroll
        for (int o = 0; o < 17; o++) {
            float2 e = unpack2(acc[o]);
            outp[o * 64] = e.x + e.y;
        }
    }

    // ---- arrival protocol (threadFenceReduction pattern, FIXED): ----
    // barrier first so ALL threads' stores happen-before tid0's release fence.
    __syncthreads();
    if (tid == 0) {
        __threadfence();                       // cumulative release of block's stores
        int old = atomicAdd(&g_cnt[img], 1);
        s_last = (old == 3);
        __threadfence();                       // acquire before consuming partials
    }
    __syncthreads();
    if (!s_last) return;

    // overlay retired smem: sc1 [y][x17][ic64] = 11968 fl ; sw2 half = 9216 fl
    float* sc1 = sm;
    float* sw2 = sm + C1PSZ;
    {
        const float4* pa = (const float4*)(g_c1h0 + (size_t)img * C1PSZ);
        const float4* pb = (const float4*)(g_c1h1 + (size_t)img * C1PSZ);
        for (int i = tid; i < C1PSZ / 4; i += 352) {
            float4 a = ldcg4(&pa[i]);
            float4 b = ldcg4(&pb[i]);
            int oc = (i * 4) & 63;
            float4 v;
            v.x = fmaxf(a.x + b.x + __ldg(&b1[oc + 0]), 0.f);
            v.y = fmaxf(a.y + b.y + __ldg(&b1[oc + 1]), 0.f);
            v.z = fmaxf(a.z + b.z + __ldg(&b1[oc + 2]), 0.f);
            v.w = fmaxf(a.w + b.w + __ldg(&b1[oc + 3]), 0.f);
            ((float4*)sc1)[i] = v;
        }
    }

    int w2w  = tid >> 5;          // warp 0..10
    int oy2  = (w2w >> 1);        // 0..4 (warp 10 idle in compute)
    int p    = w2w & 1;
    int oc2  = tid & 31;
    ull acc2[4];
    #pragma unroll
    for (int o = 0; o < 4; o++) acc2[o] = 0ull;

    const ull* swq2 = (const ull*)sw2;
    #pragma unroll 1
    for (int pass = 0; pass < 2; pass++) {
        __syncthreads();
        {   // stage half of w2: icp [pass*16, pass*16+16) = 2304 float4
            const float4* ws = (const float4*)g_w2p;
            float4* dw = (float4*)sw2;
            for (int i = tid; i < 2304; i += 352) dw[i] = ws[pass * 2304 + i];
        }
        __syncthreads();
        if (w2w < 10) {
            #pragma unroll 1
            for (int icqL = 0; icqL < 8; icqL++) {   // 4 input channels per iter
                int icq = pass * 8 + icqL;
                #pragma unroll
                for (int ky = 0; ky < 3; ky++) {
                    int r = 2 * oy2 + ky;
                    ulonglong2 t[9];
                    #pragma unroll
                    for (int j = 0; j < 9; j++)
                        t[j] = *(const ulonglong2*)&sc1[(r * 17 + 8 * p + j) * 64 + 4 * icq];
                    #pragma unroll
                    for (int kx = 0; kx < 3; kx++) {
                        ull wk0 = swq2[((2 * icqL)     * 9 + ky * 3 + kx) * 32 + oc2];
                        ull wk1 = swq2[((2 * icqL + 1) * 9 + ky * 3 + kx) * 32 + oc2];
                        #pragma unroll
                        for (int o = 0; o < 4; o++) {
                            acc2[o] = ffma2(wk0, t[2 * o + kx].x, acc2[o]);
                            acc2[o] = ffma2(wk1, t[2 * o + kx].y, acc2[o]);
                        }
                    }
                }
            }
        }
    }
    if (w2w < 10) {
        float bb = __ldg(&b2[oc2]);
        float* out = &g_x[(size_t)img * SENS + oc2 * 40 + oy2 * 8 + 4 * p];
        #pragma unroll
        for (int o = 0; o < 4; o++) {
            float2 e = unpack2(acc2[o]);
            out[o] = fmaxf(e.x + e.y + bb, 0.f);
        }
    }
    if (tid < 3)
        g_x[(size_t)img * SENS + 1280 + tid] = relpos[(size_t)img * 3 + tid];
}

// ---------------- sensory synapse precompute: 12 images/block ----------------
#define SCHUNK 96
#define SIMG   12
__global__ void __launch_bounds__(SIMG * UNITS) k_sens() {
    extern __shared__ float sm3[];
    float4* sp = (float4*)sm3;
    float*  xs = sm3 + SCHUNK * UNITS * 4;
    int tid = threadIdx.x;
    int img0 = blockIdx.x * SIMG;
    for (int i = tid; i < SIMG * SENS; i += SIMG * UNITS)
        xs[i] = g_x[(size_t)img0 * SENS + i];
    int u = tid % UNITS, t = tid / UNITS;
    float accn = 0.f, accd = 0.f;
    const float* xrow = &xs[t * SENS];
    for (int k0 = 0; k0 < SENS; k0 += SCHUNK) {
        int C = min(SCHUNK, SENS - k0);
        __syncthreads();
        for (int i = tid; i < C * UNITS; i += SIMG * UNITS) sp[i] = g_sp[k0 * UNITS + i];
        __syncthreads();
        #pragma unroll 4
        for (int kk = 0; kk < C; kk++) {
            float4 p = sp[kk * UNITS + u];
            float xv = xrow[k0 + kk];
            float tt = tanhf_a(fmaf(xv, p.x, p.y));
            accn = fmaf(p.z, tt, accn);
            accd = fmaf(p.w, tt, accd);
        }
    }
    g_sn[(size_t)(img0 + t) * UNITS + u] = g_skn[u] + accn;
    g_sd[(size_t)(img0 + t) * UNITS + u] = g_skd[u] + accd;
}

// ---------------- LTC recurrence + pooling + head ----------------
__global__ void __launch_bounds__(288) k_ltc(const float* __restrict__ wout,
                                             const float* __restrict__ bout,
                                             const float* __restrict__ whead,
                                             const float* __restrict__ bhead,
                                             float* __restrict__ out) {
    extern __shared__ float sm4[];
    float4* rp   = (float4*)sm4;
    float*  sn   = sm4 + 9216;
    float*  sd   = sn + 2304;
    float*  v    = sd + 2304;
    float*  redn = v + 48;
    float*  redd = redn + 288;
    float*  cmt  = redd + 288;
    float*  nc   = cmt + 48;
    float*  dc   = nc + 48;
    float*  outsum = dc + 48;
    int b = blockIdx.x, tid = threadIdx.x;
    for (int i = tid; i < UNITS * UNITS; i += 288) rp[i] = g_rp[i];
    for (int i = tid; i < NS * UNITS; i += 288) {
        sn[i] = g_sn[(size_t)b * NS * UNITS + i];
        sd[i] = g_sd[(size_t)b * NS * UNITS + i];
    }
    if (tid < UNITS) {
        v[tid] = 0.f;
        cmt[tid] = g_cmt[tid];
        nc[tid]  = g_nc[tid];
        dc[tid]  = g_dc[tid];
    }
    if (tid < 4) outsum[tid] = 0.f;
    __syncthreads();
    int u = tid % UNITS, g = tid / UNITS;
    for (int s = 0; s < NS; s++) {
        for (int it = 0; it < 6; it++) {
            float accn = 0.f, accd = 0.f;
            #pragma unroll
            for (int j = 0; j < 8; j++) {
                int p = g * 8 + j;
                float4 q = rp[p * UNITS + u];
                float tt = tanhf_a(fmaf(v[p], q.x, q.y));
                accn = fmaf(q.z, tt, accn);
                accd = fmaf(q.w, tt, accd);
            }
            redn[g * UNITS + u] = accn;
            redd[g * UNITS + u] = accd;
            __syncthreads();
            if (tid < UNITS) {
                float a = 0.f, d = 0.f;
                #pragma unroll
                for (int gg = 0; gg < 6; gg++) { a += redn[gg * UNITS + tid]; d += redd[gg * UNITS + tid]; }
                float vv  = v[tid];
                float num = fmaf(cmt[tid], vv, nc[tid]) + a + sn[s * UNITS + tid];
                float den = dc[tid] + d + sd[s * UNITS + tid];
                v[tid] = num * rcpf(den);
            }
            __syncthreads();
        }
        if (tid < 4) outsum[tid] += v[tid];
    }
    __syncthreads();
    if (tid == 0) {
        float p[4];
        #pragma unroll
        for (int m = 0; m < 4; m++)
            p[m] = outsum[m] * (1.f / 48.f) * wout[m] + bout[m];
        #pragma unroll
        for (int j = 0; j < 2; j++) {
            float h = bhead[j];
            #pragma unroll
            for (int m = 0; m < 4; m++) h = fmaf(p[m], whead[m * 2 + j], h);
            out[b * 2 + j] = tanhf(h);
        }
    }
}

// ---------------- launch ----------------
extern "C" void kernel_launch(void* const* d_in, const int* in_sizes, int n_in,
                              void* d_out, int out_size) {
    const float* image   = (const float*)d_in[0];
    const float* rel_pos = (const float*)d_in[1];
    const float* w0 = (const float*)d_in[2];
    const float* b0 = (const float*)d_in[3];
    const float* w1 = (const float*)d_in[4];
    const float* b1 = (const float*)d_in[5];
    const float* w2 = (const float*)d_in[6];
    const float* b2 = (const float*)d_in[7];
    const float* input_w = (const float*)d_in[8];
    const float* input_b = (const float*)d_in[9];
    const float* gleak = (const float*)d_in[10];
    const float* vleak = (const float*)d_in[11];
    const float* cm    = (const float*)d_in[12];
    const float* sigma = (const float*)d_in[13];
    const float* mu    = (const float*)d_in[14];
    const float* w_syn = (const float*)d_in[15];
    const float* erev  = (const float*)d_in[16];
    const float* s_sigma = (const float*)d_in[17];
    const float* s_mu    = (const float*)d_in[18];
    const float* s_w     = (const float*)d_in[19];
    const float* s_erev  = (const float*)d_in[20];
    const float* w_out = (const float*)d_in[21];
    const float* b_out = (const float*)d_in[22];
    const float* w_head = (const float*)d_in[23];
    const float* b_head = (const float*)d_in[24];
    const int* syn_mask  = (const int*)d_in[25];
    const int* sens_mask = (const int*)d_in[26];
    float* out = (float*)d_out;

    const int SM_CNN  = (3456 + 288 + 4608 + SC0H) * 4;        // 86400
    const int SM_SENS = SCHUNK * UNITS * 16 + SIMG * SENS * 4;
    const int SM_LTC  = (9216 + 2304 + 2304 + 48 + 288 + 288 + 48 + 48 + 48 + 4) * 4;
    cudaFuncSetAttribute(k_cnn,  cudaFuncAttributeMaxDynamicSharedMemorySize, SM_CNN);
    cudaFuncSetAttribute(k_sens, cudaFuncAttributeMaxDynamicSharedMemorySize, SM_SENS);
    cudaFuncSetAttribute(k_ltc,  cudaFuncAttributeMaxDynamicSharedMemorySize, SM_LTC);

    const int NRW = 2304 + 16 * 9 * 64 + 32 * 9 * 32;
    // k_cnn kept as the 4th launch (the one ncu captures)
    k_prep_sens<<<(SENS * UNITS + 255) / 256, 256>>>(input_w, input_b, s_sigma, s_mu,
                                                     s_w, s_erev, sens_mask);
    k_prep_recw<<<(NRW + 255) / 256, 256>>>(sigma, mu, w_syn, erev, syn_mask, w1, w2);
    k_prep_const<<<UNITS, 256>>>(gleak, vleak, cm);
    k_cnn<<<dim3(4, NIMG), 352, SM_CNN>>>(image, w0, b0, b1, b2, rel_pos);
    k_sens<<<NIMG / SIMG, SIMG * UNITS, SM_SENS>>>();
    k_ltc<<<NB, 288, SM_LTC>>>(w_out, b_out, w_head, b_head, out);
}

// round 15
// speedup vs baseline: 1.1929x; 1.0194x over previous
#include <cuda_runtime.h>
#include <math.h>

typedef unsigned long long ull;

// ---------------- problem constants ----------------
#define NIMG   1536            // B*S
#define UNITS  48
#define SENS   1283
#define NB     32
#define NS     48
#define H0 48
#define W0 72

// sc0 half: [icpL=8][row 23][pos 0..35][2ic] ; PSTR=72 floats (288B)
#define PSTR 72
#define PLN  (23*PSTR)          // 1656 floats per plane
#define SC0H (8*PLN)            // 13248 floats
#define W1PSZ (16*9*64*2)       // 18432 floats: ull[g=icp*9+j][2*lane+s]
#define W2PSZ (32*9*32*2)       // 18432 floats: [icp32][j9][oc32] ull
#define C1PSZ (11*17*64)        // 11968 floats/img: [y][x17][oc64] FINAL conv1

// ---------------- device scratch ----------------
__device__ float  g_c1[(size_t)NIMG * C1PSZ];       // conv1 final (bias+relu)
__device__ float  g_x [(size_t)NIMG * SENS];
__device__ float  g_sn[(size_t)NIMG * UNITS];
__device__ float  g_sd[(size_t)NIMG * UNITS];
__device__ float4 g_sp[SENS * UNITS];
__device__ float4 g_rp[UNITS * UNITS];
__device__ float  g_skn[UNITS], g_skd[UNITS];
__device__ float  g_nc[UNITS], g_dc[UNITS], g_cmt[UNITS];
__device__ float  g_w1p[W1PSZ];
__device__ ull    g_w2p[W2PSZ / 2];

// ---------------- fast math helpers ----------------
__device__ __forceinline__ float rcpf(float x) {
    float y; asm("rcp.approx.f32 %0, %1;" : "=f"(y) : "f"(x)); return y;
}
__device__ __forceinline__ float tanhf_a(float x) {
    float y; asm("tanh.approx.f32 %0, %1;" : "=f"(y) : "f"(x)); return y;
}
__device__ __forceinline__ ull ffma2(ull a, ull b, ull c) {
    ull d; asm("fma.rn.f32x2 %0, %1, %2, %3;" : "=l"(d) : "l"(a), "l"(b), "l"(c));
    return d;
}
__device__ __forceinline__ float2 unpack2(ull v) {
    float2 r; asm("mov.b64 {%0, %1}, %2;" : "=f"(r.x), "=f"(r.y) : "l"(v));
    return r;
}

// ---------------- prep kernels ----------------
__global__ void k_prep_sens(const float* __restrict__ iw, const float* __restrict__ ib,
                            const float* __restrict__ ssig, const float* __restrict__ smu,
                            const float* __restrict__ sw, const float* __restrict__ serev,
                            const int* __restrict__ smask) {
    int idx = blockIdx.x * blockDim.x + threadIdx.x;
    if (idx >= SENS * UNITS) return;
    int k = idx / UNITS;
    float sg = ssig[idx], m = smu[idx];
    float w  = sw[idx] * (float)smask[idx];
    float A = 0.5f * sg * iw[k];
    float C = 0.5f * sg * (ib[k] - m);
    g_sp[idx] = make_float4(A, C, 0.5f * w * serev[idx], 0.5f * w);
}

// rec params + both conv weight repacks in one launch
// w1 layout: ull u = g*64 + 2*lane + s ; oc = lane + 32*s ; g = icp*9 + j
__global__ void k_prep_recw(const float* __restrict__ sigma, const float* __restrict__ mu,
                            const float* __restrict__ wsyn, const float* __restrict__ erev,
                            const int* __restrict__ mask,
                            const float* __restrict__ w1, const float* __restrict__ w2) {
    int idx = blockIdx.x * blockDim.x + threadIdx.x;
    if (idx < UNITS * UNITS) {
        float sg = sigma[idx], m = mu[idx];
        float w  = wsyn[idx] * (float)mask[idx];
        g_rp[idx] = make_float4(0.5f * sg, -0.5f * sg * m, 0.5f * w * erev[idx], 0.5f * w);
    } else if (idx < 2304 + 16 * 9 * 64) {
        int u = idx - 2304;                       // ull index 0..9215
        int q = u & 63;
        int oc = (q >> 1) + 32 * (q & 1);
        int g = u >> 6, icp = g / 9, j = g % 9;
        g_w1p[u * 2 + 0] = w1[(oc * 32 + 2 * icp) * 9 + j];
        g_w1p[u * 2 + 1] = w1[(oc * 32 + 2 * icp + 1) * 9 + j];
    } else if (idx < 2304 + 16 * 9 * 64 + 32 * 9 * 32) {
        int k = idx - 2304 - 16 * 9 * 64;         // [icp][j][oc] for conv2
        int icp = k / 288, rem = k % 288, j = rem / 32, oc = rem % 32;
        float* dst = (float*)g_w2p;
        dst[k * 2 + 0] = w2[(oc * 64 + 2 * icp) * 9 + j];
        dst[k * 2 + 1] = w2[(oc * 64 + 2 * icp + 1) * 9 + j];
    }
}

__global__ void __launch_bounds__(256) k_prep_const(const float* __restrict__ gleak,
                                                    const float* __restrict__ vleak,
                                                    const float* __restrict__ cm) {
    int u = blockIdx.x, tid = threadIdx.x;
    float kn = 0.f, kd = 0.f;
    for (int k = tid; k < SENS; k += 256) {
        float4 p = g_sp[k * UNITS + u];
        kn += p.z; kd += p.w;
    }
    #pragma unroll
    for (int o = 16; o > 0; o >>= 1) {
        kn += __shfl_xor_sync(0xffffffff, kn, o);
        kd += __shfl_xor_sync(0xffffffff, kd, o);
    }
    __shared__ float swn[8], swd[8];
    if ((tid & 31) == 0) { swn[tid >> 5] = kn; swd[tid >> 5] = kd; }
    __syncthreads();
    if (tid == 0) {
        float tn = 0.f, td = 0.f;
        #pragma unroll
        for (int i = 0; i < 8; i++) { tn += swn[i]; td += swd[i]; }
        g_skn[u] = tn; g_skd[u] = td;
        float rn = 0.f, rd = 0.f;
        for (int p = 0; p < UNITS; p++) { float4 q = g_rp[p * UNITS + u]; rn += q.z; rd += q.w; }
        float cmt = cm[u] * 6.f;
        g_cmt[u] = cmt;
        g_nc[u] = gleak[u] * vleak[u] + rn;
        g_dc[u] = cmt + gleak[u] + rd + 1e-8f;
    }
}

// ---------------- k_cnn: conv0+conv1 full-K, CTA = (xh, img) ----------------
// 352 threads (11 oy-warps x 32 lanes), 2 CTAs/SM. Each lane computes 2 ocs
// (lane, lane+32) over an x-half (9 or 8 outputs). kh processed sequentially
// (conv0 8 planes -> conv1 accumulate) so full K stays in registers.
__global__ void __launch_bounds__(352, 2) k_cnn(const float* __restrict__ image,
                                                const float* __restrict__ w0,
                                                const float* __restrict__ b0,
                                                const float* __restrict__ b1) {
    extern __shared__ float sm[];
    float* simg = sm;                // 3456
    float* sw0  = sm + 3456;         // 288
    float* sw1  = sm + 3744;         // 9216 (half of w1p for current kh)
    float* sc0  = sm + 12960;        // 13248  (total 26208 fl = 104832B)
    int xh  = blockIdx.x;            // 0: x 0..8 ; 1: x 9..16
    int img = blockIdx.y;
    int tid = threadIdx.x;

    {   // stage image + conv0 weights (once)
        const float4* isrc = (const float4*)(image + (size_t)img * (H0 * W0));
        float4* d = (float4*)simg;
        for (int i = tid; i < (H0 * W0) / 4; i += 352) d[i] = isrc[i];
        for (int i = tid; i < 288; i += 352) sw0[i] = w0[i];
    }

    int oy = tid >> 5, lane = tid & 31;
    const int NOUT = xh ? 8 : 9;
    ull accA[9], accB[9];
    #pragma unroll
    for (int o = 0; o < 9; o++) { accA[o] = 0ull; accB[o] = 0ull; }

    #pragma unroll 1
    for (int kh = 0; kh < 2; kh++) {
        __syncthreads();   // prior pass reads of sw1/sc0 complete (and initial stage)
        {   // stage conv1 weight half for this kh (contiguous)
            const float4* ws = (const float4*)g_w1p;
            float4* dw = (float4*)sw1;
            for (int i = tid; i < 2304; i += 352) dw[i] = ws[kh * 2304 + i];
        }
        // ---- conv0: 8 planes (global icp = kh*8 + icpL); warp per (icpL, oy) ----
        {
            for (int task = oy; task < 184; task += 11) {
                int icpL = task / 23, oyc = task % 23;
                int icpG = kh * 8 + icpL;
                float we[9], wo[9];
                #pragma unroll
                for (int j = 0; j < 9; j++) {
                    we[j] = sw0[(2 * icpG) * 9 + j];
                    wo[j] = sw0[(2 * icpG + 1) * 9 + j];
                }
                float be = __ldg(&b0[2 * icpG]), bo = __ldg(&b0[2 * icpG + 1]);
                float2* dst = (float2*)&sc0[icpL * PLN + oyc * PSTR];
                {
                    float ae = be, ao = bo;
                    #pragma unroll
                    for (int ky = 0; ky < 3; ky++) {
                        const float* row = &simg[(2 * oyc + ky) * W0 + 2 * lane];
                        #pragma unroll
                        for (int kx = 0; kx < 3; kx++) {
                            float r = row[kx];
                            ae = fmaf(we[ky * 3 + kx], r, ae);
                            ao = fmaf(wo[ky * 3 + kx], r, ao);
                        }
                    }
                    dst[lane] = make_float2(fmaxf(ae, 0.f), fmaxf(ao, 0.f));
                }
                if (lane < 3) {
                    int ox = 32 + lane;
                    float ae = be, ao = bo;
                    #pragma unroll
                    for (int ky = 0; ky < 3; ky++) {
                        const float* row = &simg[(2 * oyc + ky) * W0 + 2 * ox];
                        #pragma unroll
                        for (int kx = 0; kx < 3; kx++) {
                            float r = row[kx];
                            ae = fmaf(we[ky * 3 + kx], r, ae);
                            ao = fmaf(wo[ky * 3 + kx], r, ao);
                        }
                    }
                    dst[ox] = make_float2(fmaxf(ae, 0.f), fmaxf(ao, 0.f));
                }
            }
        }
        __syncthreads();

        // ---- conv1 accumulate over this kh's 8 planes ----
        const ull* swq = (const ull*)sw1;
        #pragma unroll 1
        for (int icpL = 0; icpL < 8; icpL++) {
            #pragma unroll
            for (int ky = 0; ky < 3; ky++) {
                int r = 2 * oy + ky;
                const ull* rb = ((const ull*)&sc0[icpL * PLN + r * PSTR]) + 18 * xh;
                ulonglong2 wv[3];
                #pragma unroll
                for (int kx = 0; kx < 3; kx++)
                    wv[kx] = *(const ulonglong2*)&swq[(icpL * 9 + ky * 3 + kx) * 64 + 2 * lane];
                {   // chunk 1: outputs 0..4 (pos 0..10 local)
                    ull t[11];
                    const ulonglong2* p2 = (const ulonglong2*)rb;
                    #pragma unroll
                    for (int j = 0; j < 5; j++) { ulonglong2 v = p2[j]; t[2 * j] = v.x; t[2 * j + 1] = v.y; }
                    t[10] = rb[10];
                    #pragma unroll
                    for (int kx = 0; kx < 3; kx++)
                        #pragma unroll
                        for (int o = 0; o < 5; o++) {
                            accA[o] = ffma2(wv[kx].x, t[2 * o + kx], accA[o]);
                            accB[o] = ffma2(wv[kx].y, t[2 * o + kx], accB[o]);
                        }
                }
                {   // chunk 2: outputs 5..NOUT-1 (pos 10..18 local; xh=1 last guarded)
                    ull t[9];
                    const ulonglong2* q2 = (const ulonglong2*)(rb + 10);
                    #pragma unroll
                    for (int j = 0; j < 4; j++) { ulonglong2 v = q2[j]; t[2 * j] = v.x; t[2 * j + 1] = v.y; }
                    t[8] = rb[18 - 18 * xh];   // xh=0: pos 18 ; xh=1: safe dummy
                    #pragma unroll
                    for (int kx = 0; kx < 3; kx++)
                        #pragma unroll
                        for (int o = 5; o < 9; o++)
                            if (o < NOUT) {
                                accA[o] = ffma2(wv[kx].x, t[2 * (o - 5) + kx], accA[o]);
                                accB[o] = ffma2(wv[kx].y, t[2 * (o - 5) + kx], accB[o]);
                            }
                }
            }
        }
    }

    // ---- epilogue: bias + relu, final conv1 -> g_c1 [y][x17][oc64] ----
    float bbA = __ldg(&b1[lane]), bbB = __ldg(&b1[lane + 32]);
    float* base = g_c1 + (size_t)img * C1PSZ + (oy * 17 + xh * 9) * 64;
    #pragma unroll
    for (int o = 0; o < 9; o++)
        if (o < NOUT) {
            float2 ea = unpack2(accA[o]);
            float2 eb = unpack2(accB[o]);
            base[o * 64 + lane]      = fmaxf(ea.x + ea.y + bbA, 0.f);
            base[o * 64 + lane + 32] = fmaxf(eb.x + eb.y + bbB, 0.f);
        }
}

// ---------------- k_conv2: L2-hot input stage + 2-pass smem weights ----------------
// 320 threads (10 warps: warp=(oy,p), lane=oc), 2 CTAs/SM.
__global__ void __launch_bounds__(320, 2) k_conv2(const float* __restrict__ b2,
                                                  const float* __restrict__ relpos) {
    extern __shared__ float sm2[];
    float* sc1 = sm2;                 // 11968, layout [y][x17][ic64] (final conv1)
    float* sw2 = sm2 + C1PSZ;         // 9216 (half of w2 per pass)
    int img = blockIdx.x, tid = threadIdx.x;
    {
        const float4* src = (const float4*)(g_c1 + (size_t)img * C1PSZ);
        float4* d = (float4*)sc1;
        for (int i = tid; i < C1PSZ / 4; i += 320) d[i] = src[i];
    }

    int w    = tid >> 5;          // 0..9
    int oy   = w >> 1;            // 0..4
    int p    = w & 1;             // 0..1
    int oc2  = tid & 31;          // 0..31
    ull acc[4];
    #pragma unroll
    for (int o = 0; o < 4; o++) acc[o] = 0ull;

    const ull* swq = (const ull*)sw2;
    #pragma unroll 1
    for (int pass = 0; pass < 2; pass++) {
        __syncthreads();
        {   // stage half of w2: icp [pass*16, pass*16+16)
            const float4* ws = (const float4*)g_w2p;
            float4* dw = (float4*)sw2;
            for (int i = tid; i < 2304; i += 320) dw[i] = ws[pass * 2304 + i];
        }
        __syncthreads();
        #pragma unroll 1
        for (int icqL = 0; icqL < 8; icqL++) {   // 4 input channels per iter
            int icq = pass * 8 + icqL;
            #pragma unroll
            for (int ky = 0; ky < 3; ky++) {
                int r = 2 * oy + ky;
                ulonglong2 t[9];
                #pragma unroll
                for (int j = 0; j < 9; j++)
                    t[j] = *(const ulonglong2*)&sc1[(r * 17 + 8 * p + j) * 64 + 4 * icq];
                #pragma unroll
                for (int kx = 0; kx < 3; kx++) {
                    ull wk0 = swq[((2 * icqL)     * 9 + ky * 3 + kx) * 32 + oc2];
                    ull wk1 = swq[((2 * icqL + 1) * 9 + ky * 3 + kx) * 32 + oc2];
                    #pragma unroll
                    for (int o = 0; o < 4; o++) {
                        acc[o] = ffma2(wk0, t[2 * o + kx].x, acc[o]);
                        acc[o] = ffma2(wk1, t[2 * o + kx].y, acc[o]);
                    }
                }
            }
        }
    }
    float bb = __ldg(&b2[oc2]);
    float* out = &g_x[(size_t)img * SENS + oc2 * 40 + oy * 8 + 4 * p];
    #pragma unroll
    for (int o = 0; o < 4; o++) {
        float2 e = unpack2(acc[o]);
        out[o] = fmaxf(e.x + e.y + bb, 0.f);
    }
    if (tid < 3)
        g_x[(size_t)img * SENS + 1280 + tid] = relpos[(size_t)img * 3 + tid];
}

// ---------------- sensory synapse precompute: 12 images/block ----------------
#define SCHUNK 96
#define SIMG   12
__global__ void __launch_bounds__(SIMG * UNITS) k_sens() {
    extern __shared__ float sm3[];
    float4* sp = (float4*)sm3;
    float*  xs = sm3 + SCHUNK * UNITS * 4;
    int tid = threadIdx.x;
    int img0 = blockIdx.x * SIMG;
    for (int i = tid; i < SIMG * SENS; i += SIMG * UNITS)
        xs[i] = g_x[(size_t)img0 * SENS + i];
    int u = tid % UNITS, t = tid / UNITS;
    float accn = 0.f, accd = 0.f;
    const float* xrow = &xs[t * SENS];
    for (int k0 = 0; k0 < SENS; k0 += SCHUNK) {
        int C = min(SCHUNK, SENS - k0);
        __syncthreads();
        for (int i = tid; i < C * UNITS; i += SIMG * UNITS) sp[i] = g_sp[k0 * UNITS + i];
        __syncthreads();
        #pragma unroll 4
        for (int kk = 0; kk < C; kk++) {
            float4 p = sp[kk * UNITS + u];
            float xv = xrow[k0 + kk];
            float tt = tanhf_a(fmaf(xv, p.x, p.y));
            accn = fmaf(p.z, tt, accn);
            accd = fmaf(p.w, tt, accd);
        }
    }
    g_sn[(size_t)(img0 + t) * UNITS + u] = g_skn[u] + accn;
    g_sd[(size_t)(img0 + t) * UNITS + u] = g_skd[u] + accd;
}

// ---------------- LTC recurrence + pooling + head ----------------
__global__ void __launch_bounds__(288) k_ltc(const float* __restrict__ wout,
                                             const float* __restrict__ bout,
                                             const float* __restrict__ whead,
                                             const float* __restrict__ bhead,
                                             float* __restrict__ out) {
    extern __shared__ float sm4[];
    float4* rp   = (float4*)sm4;
    float*  sn   = sm4 + 9216;
    float*  sd   = sn + 2304;
    float*  v    = sd + 2304;
    float*  redn = v + 48;
    float*  redd = redn + 288;
    float*  cmt  = redd + 288;
    float*  nc   = cmt + 48;
    float*  dc   = nc + 48;
    float*  outsum = dc + 48;
    int b = blockIdx.x, tid = threadIdx.x;
    for (int i = tid; i < UNITS * UNITS; i += 288) rp[i] = g_rp[i];
    for (int i = tid; i < NS * UNITS; i += 288) {
        sn[i] = g_sn[(size_t)b * NS * UNITS + i];
        sd[i] = g_sd[(size_t)b * NS * UNITS + i];
    }
    if (tid < UNITS) {
        v[tid] = 0.f;
        cmt[tid] = g_cmt[tid];
        nc[tid]  = g_nc[tid];
        dc[tid]  = g_dc[tid];
    }
    if (tid < 4) outsum[tid] = 0.f;
    __syncthreads();
    int u = tid % UNITS, g = tid / UNITS;
    for (int s = 0; s < NS; s++) {
        for (int it = 0; it < 6; it++) {
            float accn = 0.f, accd = 0.f;
            #pragma unroll
            for (int j = 0; j < 8; j++) {
                int p = g * 8 + j;
                float4 q = rp[p * UNITS + u];
                float tt = tanhf_a(fmaf(v[p], q.x, q.y));
                accn = fmaf(q.z, tt, accn);
                accd = fmaf(q.w, tt, accd);
            }
            redn[g * UNITS + u] = accn;
            redd[g * UNITS + u] = accd;
            __syncthreads();
            if (tid < UNITS) {
                float a = 0.f, d = 0.f;
                #pragma unroll
                for (int gg = 0; gg < 6; gg++) { a += redn[gg * UNITS + tid]; d += redd[gg * UNITS + tid]; }
                float vv  = v[tid];
                float num = fmaf(cmt[tid], vv, nc[tid]) + a + sn[s * UNITS + tid];
                float den = dc[tid] + d + sd[s * UNITS + tid];
                v[tid] = num * rcpf(den);
            }
            __syncthreads();
        }
        if (tid < 4) outsum[tid] += v[tid];
    }
    __syncthreads();
    if (tid == 0) {
        float p[4];
        #pragma unroll
        for (int m = 0; m < 4; m++)
            p[m] = outsum[m] * (1.f / 48.f) * wout[m] + bout[m];
        #pragma unroll
        for (int j = 0; j < 2; j++) {
            float h = bhead[j];
            #pragma unroll
            for (int m = 0; m < 4; m++) h = fmaf(p[m], whead[m * 2 + j], h);
            out[b * 2 + j] = tanhf(h);
        }
    }
}

// ---------------- launch ----------------
extern "C" void kernel_launch(void* const* d_in, const int* in_sizes, int n_in,
                              void* d_out, int out_size) {
    const float* image   = (const float*)d_in[0];
    const float* rel_pos = (const float*)d_in[1];
    const float* w0 = (const float*)d_in[2];
    const float* b0 = (const float*)d_in[3];
    const float* w1 = (const float*)d_in[4];
    const float* b1 = (const float*)d_in[5];
    const float* w2 = (const float*)d_in[6];
    const float* b2 = (const float*)d_in[7];
    const float* input_w = (const float*)d_in[8];
    const float* input_b = (const float*)d_in[9];
    const float* gleak = (const float*)d_in[10];
    const float* vleak = (const float*)d_in[11];
    const float* cm    = (const float*)d_in[12];
    const float* sigma = (const float*)d_in[13];
    const float* mu    = (const float*)d_in[14];
    const float* w_syn = (const float*)d_in[15];
    const float* erev  = (const float*)d_in[16];
    const float* s_sigma = (const float*)d_in[17];
    const float* s_mu    = (const float*)d_in[18];
    const float* s_w     = (const float*)d_in[19];
    const float* s_erev  = (const float*)d_in[20];
    const float* w_out = (const float*)d_in[21];
    const float* b_out = (const float*)d_in[22];
    const float* w_head = (const float*)d_in[23];
    const float* b_head = (const float*)d_in[24];
    const int* syn_mask  = (const int*)d_in[25];
    const int* sens_mask = (const int*)d_in[26];
    float* out = (float*)d_out;

    const int SM_CNN  = (3456 + 288 + 9216 + SC0H) * 4;        // 104832
    const int SM_CV2  = (C1PSZ + 9216) * 4;                    // 84736
    const int SM_SENS = SCHUNK * UNITS * 16 + SIMG * SENS * 4;
    const int SM_LTC  = (9216 + 2304 + 2304 + 48 + 288 + 288 + 48 + 48 + 48 + 4) * 4;
    cudaFuncSetAttribute(k_cnn,   cudaFuncAttributeMaxDynamicSharedMemorySize, SM_CNN);
    cudaFuncSetAttribute(k_conv2, cudaFuncAttributeMaxDynamicSharedMemorySize, SM_CV2);
    cudaFuncSetAttribute(k_sens,  cudaFuncAttributeMaxDynamicSharedMemorySize, SM_SENS);
    cudaFuncSetAttribute(k_ltc,   cudaFuncAttributeMaxDynamicSharedMemorySize, SM_LTC);

    const int NRW = 2304 + 16 * 9 * 64 + 32 * 9 * 32;
    // k_cnn kept as the 4th launch (the one ncu captures)
    k_prep_sens<<<(SENS * UNITS + 255) / 256, 256>>>(input_w, input_b, s_sigma, s_mu,
                                                     s_w, s_erev, sens_mask);
    k_prep_recw<<<(NRW + 255) / 256, 256>>>(sigma, mu, w_syn, erev, syn_mask, w1, w2);
    k_prep_const<<<UNITS, 256>>>(gleak, vleak, cm);
    k_cnn<<<dim3(2, NIMG), 352, SM_CNN>>>(image, w0, b0, b1);
    k_conv2<<<NIMG, 320, SM_CV2>>>(b2, rel_pos);
    k_sens<<<NIMG / SIMG, SIMG * UNITS, SM_SENS>>>();
    k_ltc<<<NB, 288, SM_LTC>>>(w_out, b_out, w_head, b_head, out);
}

// round 16
// speedup vs baseline: 1.2273x; 1.0288x over previous
#include <cuda_runtime.h>
#include <math.h>

typedef unsigned long long ull;

// ---------------- problem constants ----------------
#define NIMG   1536            // B*S
#define UNITS  48
#define SENS   1283
#define NB     32
#define NS     48
#define H0 48
#define W0 72

// sc0 half: [icpL=8][row 23][pos 0..35][2ic] ; PSTR=72 floats (288B)
#define PSTR 72
#define PLN  (23*PSTR)          // 1656 floats per plane
#define SC0H (8*PLN)            // 13248 floats
#define W1PSZ (16*9*64*2)       // 18432 floats: ull[g=icp*9+j][2*lane+s]
#define W2PSZ (32*9*32*2)       // 18432 floats: [icp32][j9][oc32] ull
#define SC1H  (11*9*64)         // 6336 floats: conv1 window [y11][xl9][oc64]

// ---------------- device scratch ----------------
__device__ float  g_x [(size_t)NIMG * SENS];
__device__ float  g_sn[(size_t)NIMG * UNITS];
__device__ float  g_sd[(size_t)NIMG * UNITS];
__device__ float4 g_sp[SENS * UNITS];
__device__ float4 g_rp[UNITS * UNITS];
__device__ float  g_skn[UNITS], g_skd[UNITS];
__device__ float  g_nc[UNITS], g_dc[UNITS], g_cmt[UNITS];
__device__ float  g_w1p[W1PSZ];
__device__ ull    g_w2p[W2PSZ / 2];

// ---------------- fast math helpers ----------------
__device__ __forceinline__ float rcpf(float x) {
    float y; asm("rcp.approx.f32 %0, %1;" : "=f"(y) : "f"(x)); return y;
}
__device__ __forceinline__ float tanhf_a(float x) {
    float y; asm("tanh.approx.f32 %0, %1;" : "=f"(y) : "f"(x)); return y;
}
__device__ __forceinline__ ull ffma2(ull a, ull b, ull c) {
    ull d; asm("fma.rn.f32x2 %0, %1, %2, %3;" : "=l"(d) : "l"(a), "l"(b), "l"(c));
    return d;
}
__device__ __forceinline__ float2 unpack2(ull v) {
    float2 r; asm("mov.b64 {%0, %1}, %2;" : "=f"(r.x), "=f"(r.y) : "l"(v));
    return r;
}

// ---------------- prep kernels ----------------
__global__ void k_prep_sens(const float* __restrict__ iw, const float* __restrict__ ib,
                            const float* __restrict__ ssig, const float* __restrict__ smu,
                            const float* __restrict__ sw, const float* __restrict__ serev,
                            const int* __restrict__ smask) {
    int idx = blockIdx.x * blockDim.x + threadIdx.x;
    if (idx >= SENS * UNITS) return;
    int k = idx / UNITS;
    float sg = ssig[idx], m = smu[idx];
    float w  = sw[idx] * (float)smask[idx];
    float A = 0.5f * sg * iw[k];
    float C = 0.5f * sg * (ib[k] - m);
    g_sp[idx] = make_float4(A, C, 0.5f * w * serev[idx], 0.5f * w);
}

// rec params + both conv weight repacks in one launch
// w1 layout: ull u = g*64 + 2*lane + s ; oc = lane + 32*s ; g = icp*9 + j
__global__ void k_prep_recw(const float* __restrict__ sigma, const float* __restrict__ mu,
                            const float* __restrict__ wsyn, const float* __restrict__ erev,
                            const int* __restrict__ mask,
                            const float* __restrict__ w1, const float* __restrict__ w2) {
    int idx = blockIdx.x * blockDim.x + threadIdx.x;
    if (idx < UNITS * UNITS) {
        float sg = sigma[idx], m = mu[idx];
        float w  = wsyn[idx] * (float)mask[idx];
        g_rp[idx] = make_float4(0.5f * sg, -0.5f * sg * m, 0.5f * w * erev[idx], 0.5f * w);
    } else if (idx < 2304 + 16 * 9 * 64) {
        int u = idx - 2304;                       // ull index 0..9215
        int q = u & 63;
        int oc = (q >> 1) + 32 * (q & 1);
        int g = u >> 6, icp = g / 9, j = g % 9;
        g_w1p[u * 2 + 0] = w1[(oc * 32 + 2 * icp) * 9 + j];
        g_w1p[u * 2 + 1] = w1[(oc * 32 + 2 * icp + 1) * 9 + j];
    } else if (idx < 2304 + 16 * 9 * 64 + 32 * 9 * 32) {
        int k = idx - 2304 - 16 * 9 * 64;         // [icp][j][oc] for conv2
        int icp = k / 288, rem = k % 288, j = rem / 32, oc = rem % 32;
        float* dst = (float*)g_w2p;
        dst[k * 2 + 0] = w2[(oc * 64 + 2 * icp) * 9 + j];
        dst[k * 2 + 1] = w2[(oc * 64 + 2 * icp + 1) * 9 + j];
    }
}

__global__ void __launch_bounds__(256) k_prep_const(const float* __restrict__ gleak,
                                                    const float* __restrict__ vleak,
                                                    const float* __restrict__ cm) {
    int u = blockIdx.x, tid = threadIdx.x;
    float kn = 0.f, kd = 0.f;
    for (int k = tid; k < SENS; k += 256) {
        float4 p = g_sp[k * UNITS + u];
        kn += p.z; kd += p.w;
    }
    #pragma unroll
    for (int o = 16; o > 0; o >>= 1) {
        kn += __shfl_xor_sync(0xffffffff, kn, o);
        kd += __shfl_xor_sync(0xffffffff, kd, o);
    }
    __shared__ float swn[8], swd[8];
    if ((tid & 31) == 0) { swn[tid >> 5] = kn; swd[tid >> 5] = kd; }
    __syncthreads();
    if (tid == 0) {
        float tn = 0.f, td = 0.f;
        #pragma unroll
        for (int i = 0; i < 8; i++) { tn += swn[i]; td += swd[i]; }
        g_skn[u] = tn; g_skd[u] = td;
        float rn = 0.f, rd = 0.f;
        for (int p = 0; p < UNITS; p++) { float4 q = g_rp[p * UNITS + u]; rn += q.z; rd += q.w; }
        float cmt = cm[u] * 6.f;
        g_cmt[u] = cmt;
        g_nc[u] = gleak[u] * vleak[u] + rn;
        g_dc[u] = cmt + gleak[u] + rd + 1e-8f;
    }
}

// ---------------- k_cnn: conv0+conv1 full-K + fused conv2 half, CTA = (xh, img) ----
// 352 threads (11 oy-warps x 32 lanes), 2 CTAs/SM. Each lane: 2 ocs (lane, lane+32),
// x-window [8xh, 8xh+8] (9 outputs; overlap column x=8 computed by both CTAs).
// Tail: conv1 window -> smem, conv2 x-half computed in-CTA, writes g_x directly.
__global__ void __launch_bounds__(352, 2) k_cnn(const float* __restrict__ image,
                                                const float* __restrict__ w0,
                                                const float* __restrict__ b0,
                                                const float* __restrict__ b1,
                                                const float* __restrict__ b2,
                                                const float* __restrict__ relpos) {
    extern __shared__ float sm[];
    float* simg = sm;                // 3456
    float* sw0  = sm + 3456;         // 288
    float* sw1  = sm + 3744;         // 9216 (half of w1p for current kh)
    float* sc0  = sm + 12960;        // 13248  (total 26208 fl = 104832B)
    int xh  = blockIdx.x;            // 0: x 0..8 ; 1: x 8..16
    int img = blockIdx.y;
    int tid = threadIdx.x;

    {   // stage image + conv0 weights (once)
        const float4* isrc = (const float4*)(image + (size_t)img * (H0 * W0));
        float4* d = (float4*)simg;
        for (int i = tid; i < (H0 * W0) / 4; i += 352) d[i] = isrc[i];
        for (int i = tid; i < 288; i += 352) sw0[i] = w0[i];
    }

    int oy = tid >> 5, lane = tid & 31;
    ull accA[9], accB[9];
    #pragma unroll
    for (int o = 0; o < 9; o++) { accA[o] = 0ull; accB[o] = 0ull; }

    #pragma unroll 1
    for (int kh = 0; kh < 2; kh++) {
        __syncthreads();   // prior pass reads of sw1/sc0 complete (and initial stage)
        {   // stage conv1 weight half for this kh (contiguous)
            const float4* ws = (const float4*)g_w1p;
            float4* dw = (float4*)sw1;
            for (int i = tid; i < 2304; i += 352) dw[i] = ws[kh * 2304 + i];
        }
        // ---- conv0: 8 planes; warp per (icpL, oy); only positions 16xh..16xh+18 ----
        {
            for (int task = oy; task < 184; task += 11) {
                int icpL = task / 23, oyc = task % 23;
                int icpG = kh * 8 + icpL;
                if (lane < 19) {
                    float we[9], wo[9];
                    #pragma unroll
                    for (int j = 0; j < 9; j++) {
                        we[j] = sw0[(2 * icpG) * 9 + j];
                        wo[j] = sw0[(2 * icpG + 1) * 9 + j];
                    }
                    float ae = __ldg(&b0[2 * icpG]), ao = __ldg(&b0[2 * icpG + 1]);
                    int pos = 16 * xh + lane;
                    #pragma unroll
                    for (int ky = 0; ky < 3; ky++) {
                        const float* row = &simg[(2 * oyc + ky) * W0 + 2 * pos];
                        #pragma unroll
                        for (int kx = 0; kx < 3; kx++) {
                            float r = row[kx];
                            ae = fmaf(we[ky * 3 + kx], r, ae);
                            ao = fmaf(wo[ky * 3 + kx], r, ao);
                        }
                    }
                    float2* dst = (float2*)&sc0[icpL * PLN + oyc * PSTR];
                    dst[pos] = make_float2(fmaxf(ae, 0.f), fmaxf(ao, 0.f));
                }
            }
        }
        __syncthreads();

        // ---- conv1 accumulate over this kh's 8 planes (9 outputs, window base 16xh) ----
        const ull* swq = (const ull*)sw1;
        #pragma unroll 1
        for (int icpL = 0; icpL < 8; icpL++) {
            #pragma unroll
            for (int ky = 0; ky < 3; ky++) {
                int r = 2 * oy + ky;
                const ull* rb = ((const ull*)&sc0[icpL * PLN + r * PSTR]) + 16 * xh;
                ulonglong2 wv[3];
                #pragma unroll
                for (int kx = 0; kx < 3; kx++)
                    wv[kx] = *(const ulonglong2*)&swq[(icpL * 9 + ky * 3 + kx) * 64 + 2 * lane];
                {   // chunk 1: outputs 0..4 (local pos 0..10)
                    ull t[11];
                    const ulonglong2* p2 = (const ulonglong2*)rb;
                    #pragma unroll
                    for (int j = 0; j < 5; j++) { ulonglong2 v = p2[j]; t[2 * j] = v.x; t[2 * j + 1] = v.y; }
                    t[10] = rb[10];
                    #pragma unroll
                    for (int kx = 0; kx < 3; kx++)
                        #pragma unroll
                        for (int o = 0; o < 5; o++) {
                            accA[o] = ffma2(wv[kx].x, t[2 * o + kx], accA[o]);
                            accB[o] = ffma2(wv[kx].y, t[2 * o + kx], accB[o]);
                        }
                }
                {   // chunk 2: outputs 5..8 (local pos 10..18)
                    ull t[9];
                    const ulonglong2* q2 = (const ulonglong2*)(rb + 10);
                    #pragma unroll
                    for (int j = 0; j < 4; j++) { ulonglong2 v = q2[j]; t[2 * j] = v.x; t[2 * j + 1] = v.y; }
                    t[8] = rb[18];
                    #pragma unroll
                    for (int kx = 0; kx < 3; kx++)
                        #pragma unroll
                        for (int o = 5; o < 9; o++) {
                            accA[o] = ffma2(wv[kx].x, t[2 * (o - 5) + kx], accA[o]);
                            accB[o] = ffma2(wv[kx].y, t[2 * (o - 5) + kx], accB[o]);
                        }
                }
            }
        }
    }
    __syncthreads();   // conv1 reads of sw1/sc0 complete

    // ---- conv1 epilogue -> smem window sc1 [y11][xl9][oc64] (over dead sw1) ----
    float* sc1 = sm + 3744;              // 6336 floats
    float* sw2 = sm + 3744 + SC1H;       // 9216 floats (half of w2 per pass)
    {
        float bbA = __ldg(&b1[lane]), bbB = __ldg(&b1[lane + 32]);
        float* basep = &sc1[(oy * 9) * 64];
        #pragma unroll
        for (int o = 0; o < 9; o++) {
            float2 ea = unpack2(accA[o]);
            float2 eb = unpack2(accB[o]);
            basep[o * 64 + lane]      = fmaxf(ea.x + ea.y + bbA, 0.f);
            basep[o * 64 + lane + 32] = fmaxf(eb.x + eb.y + bbB, 0.f);
        }
    }

    // ---- conv2 x-half in-CTA: 10 warps; warp = (oy2, xg), lane = oc2; 2 outputs ----
    int w2w = tid >> 5;           // 0..10 (warp 10 idle in compute)
    int oy2 = w2w >> 1;           // 0..4
    int xg  = w2w & 1;            // 0..1
    ull acc2[2];
    acc2[0] = 0ull; acc2[1] = 0ull;
    const ull* swq2 = (const ull*)sw2;
    #pragma unroll 1
    for (int pass = 0; pass < 2; pass++) {
        __syncthreads();          // pass0: sc1 writes done ; pass1: pass0 reads done
        {   // stage half of w2: icp [pass*16, pass*16+16)
            const float4* ws = (const float4*)g_w2p;
            float4* dw = (float4*)sw2;
            for (int i = tid; i < 2304; i += 352) dw[i] = ws[pass * 2304 + i];
        }
        __syncthreads();
        if (w2w < 10) {
            #pragma unroll 1
            for (int icqL = 0; icqL < 8; icqL++) {   // 4 input channels per iter
                int icq = pass * 8 + icqL;
                #pragma unroll
                for (int ky = 0; ky < 3; ky++) {
                    int r = 2 * oy2 + ky;
                    ulonglong2 t[5];
                    #pragma unroll
                    for (int j = 0; j < 5; j++)
                        t[j] = *(const ulonglong2*)&sc1[(r * 9 + 4 * xg + j) * 64 + 4 * icq];
                    #pragma unroll
                    for (int kx = 0; kx < 3; kx++) {
                        ull wk0 = swq2[((2 * icqL)     * 9 + ky * 3 + kx) * 32 + lane];
                        ull wk1 = swq2[((2 * icqL + 1) * 9 + ky * 3 + kx) * 32 + lane];
                        #pragma unroll
                        for (int o = 0; o < 2; o++) {
                            acc2[o] = ffma2(wk0, t[2 * o + kx].x, acc2[o]);
                            acc2[o] = ffma2(wk1, t[2 * o + kx].y, acc2[o]);
                        }
                    }
                }
            }
        }
    }
    if (w2w < 10) {
        float bb = __ldg(&b2[lane]);
        float* outp = &g_x[(size_t)img * SENS + lane * 40 + oy2 * 8 + 4 * xh + 2 * xg];
        #pragma unroll
        for (int o = 0; o < 2; o++) {
            float2 e = unpack2(acc2[o]);
            outp[o] = fmaxf(e.x + e.y + bb, 0.f);
        }
    }
    if (xh == 0 && tid < 3)
        g_x[(size_t)img * SENS + 1280 + tid] = relpos[(size_t)img * 3 + tid];
}

// ---------------- sensory synapse precompute: 12 images/block ----------------
#define SCHUNK 96
#define SIMG   12
__global__ void __launch_bounds__(SIMG * UNITS) k_sens() {
    extern __shared__ float sm3[];
    float4* sp = (float4*)sm3;
    float*  xs = sm3 + SCHUNK * UNITS * 4;
    int tid = threadIdx.x;
    int img0 = blockIdx.x * SIMG;
    for (int i = tid; i < SIMG * SENS; i += SIMG * UNITS)
        xs[i] = g_x[(size_t)img0 * SENS + i];
    int u = tid % UNITS, t = tid / UNITS;
    float accn = 0.f, accd = 0.f;
    const float* xrow = &xs[t * SENS];
    for (int k0 = 0; k0 < SENS; k0 += SCHUNK) {
        int C = min(SCHUNK, SENS - k0);
        __syncthreads();
        for (int i = tid; i < C * UNITS; i += SIMG * UNITS) sp[i] = g_sp[k0 * UNITS + i];
        __syncthreads();
        #pragma unroll 4
        for (int kk = 0; kk < C; kk++) {
            float4 p = sp[kk * UNITS + u];
            float xv = xrow[k0 + kk];
            float tt = tanhf_a(fmaf(xv, p.x, p.y));
            accn = fmaf(p.z, tt, accn);
            accd = fmaf(p.w, tt, accd);
        }
    }
    g_sn[(size_t)(img0 + t) * UNITS + u] = g_skn[u] + accn;
    g_sd[(size_t)(img0 + t) * UNITS + u] = g_skd[u] + accd;
}

// ---------------- LTC recurrence + pooling + head ----------------
__global__ void __launch_bounds__(288) k_ltc(const float* __restrict__ wout,
                                             const float* __restrict__ bout,
                                             const float* __restrict__ whead,
                                             const float* __restrict__ bhead,
                                             float* __restrict__ out) {
    extern __shared__ float sm4[];
    float4* rp   = (float4*)sm4;
    float*  sn   = sm4 + 9216;
    float*  sd   = sn + 2304;
    float*  v    = sd + 2304;
    float*  redn = v + 48;
    float*  redd = redn + 288;
    float*  cmt  = redd + 288;
    float*  nc   = cmt + 48;
    float*  dc   = nc + 48;
    float*  outsum = dc + 48;
    int b = blockIdx.x, tid = threadIdx.x;
    for (int i = tid; i < UNITS * UNITS; i += 288) rp[i] = g_rp[i];
    for (int i = tid; i < NS * UNITS; i += 288) {
        sn[i] = g_sn[(size_t)b * NS * UNITS + i];
        sd[i] = g_sd[(size_t)b * NS * UNITS + i];
    }
    if (tid < UNITS) {
        v[tid] = 0.f;
        cmt[tid] = g_cmt[tid];
        nc[tid]  = g_nc[tid];
        dc[tid]  = g_dc[tid];
    }
    if (tid < 4) outsum[tid] = 0.f;
    __syncthreads();
    int u = tid % UNITS, g = tid / UNITS;
    for (int s = 0; s < NS; s++) {
        for (int it = 0; it < 6; it++) {
            float accn = 0.f, accd = 0.f;
            #pragma unroll
            for (int j = 0; j < 8; j++) {
                int p = g * 8 + j;
                float4 q = rp[p * UNITS + u];
                float tt = tanhf_a(fmaf(v[p], q.x, q.y));
                accn = fmaf(q.z, tt, accn);
                accd = fmaf(q.w, tt, accd);
            }
            redn[g * UNITS + u] = accn;
            redd[g * UNITS + u] = accd;
            __syncthreads();
            if (tid < UNITS) {
                float a = 0.f, d = 0.f;
                #pragma unroll
                for (int gg = 0; gg < 6; gg++) { a += redn[gg * UNITS + tid]; d += redd[gg * UNITS + tid]; }
                float vv  = v[tid];
                float num = fmaf(cmt[tid], vv, nc[tid]) + a + sn[s * UNITS + tid];
                float den = dc[tid] + d + sd[s * UNITS + tid];
                v[tid] = num * rcpf(den);
            }
            __syncthreads();
        }
        if (tid < 4) outsum[tid] += v[tid];
    }
    __syncthreads();
    if (tid == 0) {
        float p[4];
        #pragma unroll
        for (int m = 0; m < 4; m++)
            p[m] = outsum[m] * (1.f / 48.f) * wout[m] + bout[m];
        #pragma unroll
        for (int j = 0; j < 2; j++) {
            float h = bhead[j];
            #pragma unroll
            for (int m = 0; m < 4; m++) h = fmaf(p[m], whead[m * 2 + j], h);
            out[b * 2 + j] = tanhf(h);
        }
    }
}

// ---------------- launch ----------------
extern "C" void kernel_launch(void* const* d_in, const int* in_sizes, int n_in,
                              void* d_out, int out_size) {
    const float* image   = (const float*)d_in[0];
    const float* rel_pos = (const float*)d_in[1];
    const float* w0 = (const float*)d_in[2];
    const float* b0 = (const float*)d_in[3];
    const float* w1 = (const float*)d_in[4];
    const float* b1 = (const float*)d_in[5];
    const float* w2 = (const float*)d_in[6];
    const float* b2 = (const float*)d_in[7];
    const float* input_w = (const float*)d_in[8];
    const float* input_b = (const float*)d_in[9];
    const float* gleak = (const float*)d_in[10];
    const float* vleak = (const float*)d_in[11];
    const float* cm    = (const float*)d_in[12];
    const float* sigma = (const float*)d_in[13];
    const float* mu    = (const float*)d_in[14];
    const float* w_syn = (const float*)d_in[15];
    const float* erev  = (const float*)d_in[16];
    const float* s_sigma = (const float*)d_in[17];
    const float* s_mu    = (const float*)d_in[18];
    const float* s_w     = (const float*)d_in[19];
    const float* s_erev  = (const float*)d_in[20];
    const float* w_out = (const float*)d_in[21];
    const float* b_out = (const float*)d_in[22];
    const float* w_head = (const float*)d_in[23];
    const float* b_head = (const float*)d_in[24];
    const int* syn_mask  = (const int*)d_in[25];
    const int* sens_mask = (const int*)d_in[26];
    float* out = (float*)d_out;

    const int SM_CNN  = (3456 + 288 + 9216 + SC0H) * 4;        // 104832
    const int SM_SENS = SCHUNK * UNITS * 16 + SIMG * SENS * 4;
    const int SM_LTC  = (9216 + 2304 + 2304 + 48 + 288 + 288 + 48 + 48 + 48 + 4) * 4;
    cudaFuncSetAttribute(k_cnn,  cudaFuncAttributeMaxDynamicSharedMemorySize, SM_CNN);
    cudaFuncSetAttribute(k_sens, cudaFuncAttributeMaxDynamicSharedMemorySize, SM_SENS);
    cudaFuncSetAttribute(k_ltc,  cudaFuncAttributeMaxDynamicSharedMemorySize, SM_LTC);

    const int NRW = 2304 + 16 * 9 * 64 + 32 * 9 * 32;
    // k_cnn kept as the 4th launch (the one ncu captures)
    k_prep_sens<<<(SENS * UNITS + 255) / 256, 256>>>(input_w, input_b, s_sigma, s_mu,
                                                     s_w, s_erev, sens_mask);
    k_prep_recw<<<(NRW + 255) / 256, 256>>>(sigma, mu, w_syn, erev, syn_mask, w1, w2);
    k_prep_const<<<UNITS, 256>>>(gleak, vleak, cm);
    k_cnn<<<dim3(2, NIMG), 352, SM_CNN>>>(image, w0, b0, b1, b2, rel_pos);
    k_sens<<<NIMG / SIMG, SIMG * UNITS, SM_SENS>>>();
    k_ltc<<<NB, 288, SM_LTC>>>(w_out, b_out, w_head, b_head, out);
}